// round 2
// baseline (speedup 1.0000x reference)
#include <cuda_runtime.h>

#define NN 50000
#define NE 800000
#define HIDD 128
#define NG 512

// ---------------- scratch (no allocations allowed) ----------------
__device__ float g_agg[(size_t)NN * HIDD];
__device__ float g_h1[(size_t)NN * HIDD];
__device__ float g_h2[(size_t)NN * HIDD];
__device__ float g_cnt[NN];
__device__ float g_pool[NG * HIDD];
__device__ int g_src[NE];
__device__ int g_dst[NE];
__device__ int g_bat[NN];
__device__ int g_eflag;   // 1 => edge_index stored as int32
__device__ int g_bflag;   // 1 => batch stored as int32

// ---------------- zero / detect / convert ----------------
__global__ void zero_all_kernel() {
    long long i = (long long)blockIdx.x * blockDim.x + threadIdx.x;
    long long stride = (long long)gridDim.x * blockDim.x;
    if (i == 0) { g_eflag = 0; g_bflag = 0; }
    for (long long j = i; j < (long long)NN * HIDD; j += stride) g_agg[j] = 0.f;
    for (long long j = i; j < NN; j += stride) g_cnt[j] = 0.f;
    for (long long j = i; j < NG * HIDD; j += stride) g_pool[j] = 0.f;
}

__global__ void zero_agg_kernel() {
    long long i = (long long)blockIdx.x * blockDim.x + threadIdx.x;
    long long stride = (long long)gridDim.x * blockDim.x;
    for (long long j = i; j < (long long)NN * HIDD; j += stride) g_agg[j] = 0.f;
}

// Sample 64-bit words: true int64 indices are < 50000, so any word >= 2^32
// means the buffer actually holds packed int32 values.
__global__ void detect_kernel(const unsigned long long* __restrict__ e_raw,
                              const unsigned long long* __restrict__ b_raw) {
    int i = blockIdx.x * blockDim.x + threadIdx.x;
    if (i < 4096) {
        if (e_raw[i] >= (1ull << 32)) atomicExch(&g_eflag, 1);
        if (i < 2048 && b_raw[i] >= (1ull << 32)) atomicExch(&g_bflag, 1);
    }
}

__global__ void convert_kernel(const void* __restrict__ e_raw,
                               const void* __restrict__ b_raw) {
    int eflag = g_eflag, bflag = g_bflag;
    long long i = (long long)blockIdx.x * blockDim.x + threadIdx.x;
    long long stride = (long long)gridDim.x * blockDim.x;
    for (long long e = i; e < NE; e += stride) {
        if (eflag) {
            g_src[e] = ((const int*)e_raw)[e];
            g_dst[e] = ((const int*)e_raw)[NE + e];
        } else {
            g_src[e] = (int)((const long long*)e_raw)[e];
            g_dst[e] = (int)((const long long*)e_raw)[NE + e];
        }
    }
    for (long long n = i; n < NN; n += stride) {
        g_bat[n] = bflag ? ((const int*)b_raw)[n]
                         : (int)((const long long*)b_raw)[n];
    }
}

// ---------------- edge aggregation: warp per edge ----------------
__global__ void agg_kernel(const float* __restrict__ feat,
                           float* __restrict__ aggout,
                           int with_cnt) {
    int lane = threadIdx.x & 31;
    int e = (int)((blockIdx.x * (long long)blockDim.x + threadIdx.x) >> 5);
    if (e >= NE) return;
    long long s = g_src[e];
    long long d = g_dst[e];
    float4 v = ((const float4*)(feat + s * HIDD))[lane];
    float* p = aggout + d * HIDD + lane * 4;
    asm volatile("red.global.add.v4.f32 [%0], {%1,%2,%3,%4};"
                 :: "l"(p), "f"(v.x), "f"(v.y), "f"(v.z), "f"(v.w)
                 : "memory");
    if (with_cnt && lane == 0) atomicAdd(&g_cnt[d], 1.0f);
}

// ---------------- fused SAGE conv GEMM ----------------
// out[i][c] = bl[c] + sum_k (agg[i][k]/max(cnt[i],1)) * Wl[c][k]
//                   + sum_k xin[i][k] * Wr[c][k]
#define WPAD 132
#define CONV_SMEM_FLOATS (2 * 128 * WPAD + 2 * 8 * 128)
#define CONV_SMEM_BYTES (CONV_SMEM_FLOATS * 4)

__global__ void __launch_bounds__(256) conv_kernel(
    const float* __restrict__ aggm, const float* __restrict__ xin,
    const float* __restrict__ Wl, const float* __restrict__ bl,
    const float* __restrict__ Wr, float* __restrict__ outp) {
    extern __shared__ float sm[];
    float* sWl = sm;                    // 128 x 132
    float* sWr = sm + 128 * WPAD;       // 128 x 132
    float* sM  = sWr + 128 * WPAD;      // 8 x 128
    float* sX  = sM + 8 * 128;          // 8 x 128

    int tid = threadIdx.x;

    for (int i = tid; i < 128 * 32; i += 256) {
        int c = i >> 5, q = i & 31;
        float4 vl = ((const float4*)Wl)[c * 32 + q];
        float4 vr = ((const float4*)Wr)[c * 32 + q];
        *(float4*)&sWl[c * WPAD + q * 4] = vl;
        *(float4*)&sWr[c * WPAD + q * 4] = vr;
    }
    __syncthreads();

    int cc = tid & 127;
    int grp = tid >> 7;          // 0 or 1
    float bias = bl[cc];
    const float* wlp = &sWl[cc * WPAD];
    const float* wrp = &sWr[cc * WPAD];
    const float* m0 = &sM[(grp * 4 + 0) * 128];
    const float* m1 = &sM[(grp * 4 + 1) * 128];
    const float* m2 = &sM[(grp * 4 + 2) * 128];
    const float* m3 = &sM[(grp * 4 + 3) * 128];
    const float* x0 = &sX[(grp * 4 + 0) * 128];
    const float* x1 = &sX[(grp * 4 + 1) * 128];
    const float* x2 = &sX[(grp * 4 + 2) * 128];
    const float* x3 = &sX[(grp * 4 + 3) * 128];

    for (int base = blockIdx.x * 8; base < NN; base += gridDim.x * 8) {
        {
            int r = tid >> 5, q = tid & 31;   // 8 rows x 32 quads
            int row = base + r;
            float4 mv = make_float4(0.f, 0.f, 0.f, 0.f);
            float4 xv = mv;
            if (row < NN) {
                float inv = 1.0f / fmaxf(g_cnt[row], 1.0f);
                float4 a = ((const float4*)aggm)[(long long)row * 32 + q];
                mv = make_float4(a.x * inv, a.y * inv, a.z * inv, a.w * inv);
                xv = ((const float4*)xin)[(long long)row * 32 + q];
            }
            *(float4*)&sM[r * 128 + q * 4] = mv;
            *(float4*)&sX[r * 128 + q * 4] = xv;
        }
        __syncthreads();

        float acc0 = bias, acc1 = bias, acc2 = bias, acc3 = bias;
        #pragma unroll 8
        for (int k = 0; k < 128; k += 4) {
            float4 wl = *(const float4*)(wlp + k);
            float4 wr = *(const float4*)(wrp + k);
            float4 a;
            a = *(const float4*)(m0 + k);
            acc0 += wl.x * a.x + wl.y * a.y + wl.z * a.z + wl.w * a.w;
            a = *(const float4*)(x0 + k);
            acc0 += wr.x * a.x + wr.y * a.y + wr.z * a.z + wr.w * a.w;
            a = *(const float4*)(m1 + k);
            acc1 += wl.x * a.x + wl.y * a.y + wl.z * a.z + wl.w * a.w;
            a = *(const float4*)(x1 + k);
            acc1 += wr.x * a.x + wr.y * a.y + wr.z * a.z + wr.w * a.w;
            a = *(const float4*)(m2 + k);
            acc2 += wl.x * a.x + wl.y * a.y + wl.z * a.z + wl.w * a.w;
            a = *(const float4*)(x2 + k);
            acc2 += wr.x * a.x + wr.y * a.y + wr.z * a.z + wr.w * a.w;
            a = *(const float4*)(m3 + k);
            acc3 += wl.x * a.x + wl.y * a.y + wl.z * a.z + wl.w * a.w;
            a = *(const float4*)(x3 + k);
            acc3 += wr.x * a.x + wr.y * a.y + wr.z * a.z + wr.w * a.w;
        }
        __syncthreads();

        int row0 = base + grp * 4;
        if (row0 + 0 < NN) outp[(long long)(row0 + 0) * 128 + cc] = acc0;
        if (row0 + 1 < NN) outp[(long long)(row0 + 1) * 128 + cc] = acc1;
        if (row0 + 2 < NN) outp[(long long)(row0 + 2) * 128 + cc] = acc2;
        if (row0 + 3 < NN) outp[(long long)(row0 + 3) * 128 + cc] = acc3;
    }
}

// ---------------- global add pool: warp per node ----------------
__global__ void pool_kernel(const float* __restrict__ h) {
    int lane = threadIdx.x & 31;
    int i = (int)((blockIdx.x * (long long)blockDim.x + threadIdx.x) >> 5);
    if (i >= NN) return;
    long long b = g_bat[i];
    float4 v = ((const float4*)(h + (long long)i * HIDD))[lane];
    float* p = g_pool + b * HIDD + lane * 4;
    asm volatile("red.global.add.v4.f32 [%0], {%1,%2,%3,%4};"
                 :: "l"(p), "f"(v.x), "f"(v.y), "f"(v.z), "f"(v.w)
                 : "memory");
}

// ---------------- head: lin1 + BN(eval) + relu + lin2 ----------------
__global__ void __launch_bounds__(128) head_kernel(
    const float* __restrict__ lin1w, const float* __restrict__ lin1b,
    const float* __restrict__ lin2w, const float* __restrict__ lin2b,
    const float* __restrict__ gamma, const float* __restrict__ beta,
    const float* __restrict__ rmean, const float* __restrict__ rvar,
    float* __restrict__ out) {
    int g = blockIdx.x;
    int c = threadIdx.x;
    __shared__ float p[128];
    __shared__ float h[128];
    p[c] = g_pool[g * 128 + c];
    __syncthreads();
    float acc = lin1b[c];
    const float* w = lin1w + c * 128;
    #pragma unroll 8
    for (int k = 0; k < 128; k++) acc += p[k] * w[k];
    acc = (acc - rmean[c]) * rsqrtf(rvar[c] + 1e-5f) * gamma[c] + beta[c];
    h[c] = fmaxf(acc, 0.f);
    __syncthreads();
    int wid = c >> 5, lane = c & 31;
    if (wid < 2) {
        const float* w2 = lin2w + wid * 128;
        float s = 0.f;
        #pragma unroll
        for (int k = lane; k < 128; k += 32) s += h[k] * w2[k];
        #pragma unroll
        for (int o = 16; o; o >>= 1) s += __shfl_xor_sync(0xffffffffu, s, o);
        if (lane == 0) out[g * 2 + wid] = s + lin2b[wid];
    }
}

// ---------------- launch ----------------
extern "C" void kernel_launch(void* const* d_in, const int* in_sizes, int n_in,
                              void* d_out, int out_size) {
    const float* x        = (const float*)d_in[0];
    const void*  ei_raw   = (const void*)d_in[1];
    const void*  bat_raw  = (const void*)d_in[2];
    const float* W1l      = (const float*)d_in[3];
    const float* b1       = (const float*)d_in[4];
    const float* W1r      = (const float*)d_in[5];
    const float* W2l      = (const float*)d_in[6];
    const float* b2       = (const float*)d_in[7];
    const float* W2r      = (const float*)d_in[8];
    const float* lin1w    = (const float*)d_in[9];
    const float* lin1b    = (const float*)d_in[10];
    const float* lin2w    = (const float*)d_in[11];
    const float* lin2b    = (const float*)d_in[12];
    const float* gamma    = (const float*)d_in[13];
    const float* beta     = (const float*)d_in[14];
    const float* rmean    = (const float*)d_in[15];
    const float* rvar     = (const float*)d_in[16];
    float* out            = (float*)d_out;

    float *agg, *h1, *h2;
    cudaGetSymbolAddress((void**)&agg, g_agg);
    cudaGetSymbolAddress((void**)&h1, g_h1);
    cudaGetSymbolAddress((void**)&h2, g_h2);

    cudaFuncSetAttribute(conv_kernel,
                         cudaFuncAttributeMaxDynamicSharedMemorySize,
                         CONV_SMEM_BYTES);

    const int agg_grid = (NE * 32 + 255) / 256;    // 1 edge per warp
    const int pool_grid = (NN * 32 + 255) / 256;   // 1 node per warp

    zero_all_kernel<<<2048, 256>>>();
    detect_kernel<<<16, 256>>>((const unsigned long long*)ei_raw,
                               (const unsigned long long*)bat_raw);
    convert_kernel<<<1024, 256>>>(ei_raw, bat_raw);
    agg_kernel<<<agg_grid, 256>>>(x, agg, 1);
    conv_kernel<<<148, 256, CONV_SMEM_BYTES>>>(agg, x, W1l, b1, W1r, h1);
    zero_agg_kernel<<<2048, 256>>>();
    agg_kernel<<<agg_grid, 256>>>(h1, agg, 0);
    conv_kernel<<<148, 256, CONV_SMEM_BYTES>>>(agg, h1, W2l, b2, W2r, h2);
    pool_kernel<<<pool_grid, 256>>>(h2);
    head_kernel<<<NG, 128>>>(lin1w, lin1b, lin2w, lin2b,
                             gamma, beta, rmean, rvar, out);
}

// round 4
// speedup vs baseline: 1.6389x; 1.6389x over previous
#include <cuda_runtime.h>
#include <cuda_bf16.h>
#include <cstdint>

#define NN 50000
#define NE 800000
#define NG 512

// ---------------- scratch ----------------
__device__ float g_agg[(size_t)NN * 128];
__device__ float g_h1[(size_t)NN * 128];
__device__ float g_cnt[NN];
__device__ float g_pool[NG * 128];
__device__ int g_src[NE];
__device__ int g_dst[NE];
__device__ int g_bat[NN];
__device__ int g_eflag;
__device__ int g_bflag;

// ---------------- zero / detect / convert ----------------
__global__ void zero_all_kernel() {
    long long i = (long long)blockIdx.x * blockDim.x + threadIdx.x;
    long long stride = (long long)gridDim.x * blockDim.x;
    if (i == 0) { g_eflag = 0; g_bflag = 0; }
    for (long long j = i; j < (long long)NN * 128; j += stride) g_agg[j] = 0.f;
    for (long long j = i; j < NN; j += stride) g_cnt[j] = 0.f;
    for (long long j = i; j < NG * 128; j += stride) g_pool[j] = 0.f;
}

__global__ void zero_agg_kernel() {
    long long i = (long long)blockIdx.x * blockDim.x + threadIdx.x;
    long long stride = (long long)gridDim.x * blockDim.x;
    for (long long j = i; j < (long long)NN * 128; j += stride) g_agg[j] = 0.f;
}

__global__ void detect_kernel(const unsigned long long* __restrict__ e_raw,
                              const unsigned long long* __restrict__ b_raw) {
    int i = blockIdx.x * blockDim.x + threadIdx.x;
    if (i < 4096) {
        if (e_raw[i] >= (1ull << 32)) atomicExch(&g_eflag, 1);
        if (i < 2048 && b_raw[i] >= (1ull << 32)) atomicExch(&g_bflag, 1);
    }
}

__global__ void convert_kernel(const void* __restrict__ e_raw,
                               const void* __restrict__ b_raw) {
    int eflag = g_eflag, bflag = g_bflag;
    long long i = (long long)blockIdx.x * blockDim.x + threadIdx.x;
    long long stride = (long long)gridDim.x * blockDim.x;
    for (long long e = i; e < NE; e += stride) {
        if (eflag) {
            g_src[e] = ((const int*)e_raw)[e];
            g_dst[e] = ((const int*)e_raw)[NE + e];
        } else {
            g_src[e] = (int)((const long long*)e_raw)[e];
            g_dst[e] = (int)((const long long*)e_raw)[NE + e];
        }
    }
    for (long long n = i; n < NN; n += stride) {
        g_bat[n] = bflag ? ((const int*)b_raw)[n]
                         : (int)((const long long*)b_raw)[n];
    }
}

// ---------------- edge aggregation: warp per edge ----------------
__global__ void agg_kernel(const float* __restrict__ feat,
                           float* __restrict__ aggout, int with_cnt) {
    int lane = threadIdx.x & 31;
    int e = (int)((blockIdx.x * (long long)blockDim.x + threadIdx.x) >> 5);
    if (e >= NE) return;
    long long s = g_src[e];
    long long d = g_dst[e];
    float4 v = ((const float4*)(feat + s * 128))[lane];
    float* p = aggout + d * 128 + lane * 4;
    asm volatile("red.global.add.v4.f32 [%0], {%1,%2,%3,%4};"
                 :: "l"(p), "f"(v.x), "f"(v.y), "f"(v.z), "f"(v.w) : "memory");
    if (with_cnt && lane == 0) atomicAdd(&g_cnt[d], 1.0f);
}

// ---------------- helpers ----------------
__device__ __forceinline__ void split2(float a, float b, uint32_t& hi, uint32_t& lo) {
    __nv_bfloat16 ah = __float2bfloat16(a);
    __nv_bfloat16 bh = __float2bfloat16(b);
    __nv_bfloat16 al = __float2bfloat16(a - __bfloat162float(ah));
    __nv_bfloat16 bl = __float2bfloat16(b - __bfloat162float(bh));
    hi = (uint32_t)__bfloat16_as_ushort(ah) | ((uint32_t)__bfloat16_as_ushort(bh) << 16);
    lo = (uint32_t)__bfloat16_as_ushort(al) | ((uint32_t)__bfloat16_as_ushort(bl) << 16);
}

__device__ __forceinline__ void mma16816(float* c, const uint32_t* a,
                                         uint32_t b0, uint32_t b1) {
    asm volatile(
        "mma.sync.aligned.m16n8k16.row.col.f32.bf16.bf16.f32 "
        "{%0,%1,%2,%3}, {%4,%5,%6,%7}, {%8,%9}, {%0,%1,%2,%3};"
        : "+f"(c[0]), "+f"(c[1]), "+f"(c[2]), "+f"(c[3])
        : "r"(a[0]), "r"(a[1]), "r"(a[2]), "r"(a[3]), "r"(b0), "r"(b1));
}

// ---------------- smem layout (bytes) ----------------
// A: [128 rows][136 bf16] hi/lo (34816 each). B: [128 n][264 bf16] hi/lo (67584 each).
// Epilogue f32 [128][132] reuses the A region.
#define SM_BIAS 0
#define SM_AHI  512
#define SM_ALO  35328
#define SM_EPI  512
#define SM_BHI  70144
#define SM_BLO  137728
#define SM_TOTAL 205312
#define ASTR 272     // A row stride bytes (136 bf16)
#define BSTR 528     // B row stride bytes (264 bf16)

// ---------------- fused SAGE conv via mma.sync bf16x3 ----------------
// out[i][c] = bl[c] + mean[i]@Wl[c] + xin[i]@Wr[c]   (K = 256 = [mean|x])
__global__ void __launch_bounds__(256, 1) conv_mma_kernel(
    const float* __restrict__ aggm, const float* __restrict__ xin,
    const float* __restrict__ Wl, const float* __restrict__ bl,
    const float* __restrict__ Wr, float* __restrict__ outp, int to_pool) {
    extern __shared__ char sm[];
    float* sBias = (float*)(sm + SM_BIAS);
    float* sEpi  = (float*)(sm + SM_EPI);
    int tid = threadIdx.x;
    int w = tid >> 5, lane = tid & 31;
    int quad = lane >> 2, tq = lane & 3;
    int rgrp = (w & 3) * 32;          // warp's 32 rows
    int cgrp = (w >> 2) * 64;         // warp's 64 cols

    if (tid < 128) sBias[tid] = bl[tid];

    // stage both weight matrices once: B[n][k] bf16 hi/lo, k = [Wl | Wr]
    for (int idx = tid; idx < 128 * 64; idx += 256) {
        int c = idx >> 6, p = idx & 63;
        float2 wl2 = ((const float2*)Wl)[idx];
        float2 wr2 = ((const float2*)Wr)[idx];
        uint32_t hi, lo;
        split2(wl2.x, wl2.y, hi, lo);
        *(uint32_t*)(sm + SM_BHI + c * BSTR + 4 * p) = hi;
        *(uint32_t*)(sm + SM_BLO + c * BSTR + 4 * p) = lo;
        split2(wr2.x, wr2.y, hi, lo);
        *(uint32_t*)(sm + SM_BHI + c * BSTR + 256 + 4 * p) = hi;
        *(uint32_t*)(sm + SM_BLO + c * BSTR + 256 + 4 * p) = lo;
    }
    __syncthreads();

    for (int tile = blockIdx.x; tile * 128 < NN; tile += gridDim.x) {
        int tb = tile * 128;
        float acc[2][8][4];
        #pragma unroll
        for (int rt = 0; rt < 2; rt++)
            #pragma unroll
            for (int nt = 0; nt < 8; nt++)
                #pragma unroll
                for (int j = 0; j < 4; j++) acc[rt][nt][j] = 0.f;

        #pragma unroll
        for (int h = 0; h < 2; h++) {
            // stage A k-half: h=0 -> mean, h=1 -> root
            for (int idx = tid; idx < 128 * 32; idx += 256) {
                int r = idx >> 5, q = idx & 31;
                int grow = tb + r;
                float4 v = make_float4(0.f, 0.f, 0.f, 0.f);
                if (grow < NN) {
                    if (h == 0) {
                        float inv = 1.f / fmaxf(g_cnt[grow], 1.f);
                        float4 a = ((const float4*)aggm)[(long long)grow * 32 + q];
                        v = make_float4(a.x * inv, a.y * inv, a.z * inv, a.w * inv);
                    } else {
                        v = ((const float4*)xin)[(long long)grow * 32 + q];
                    }
                }
                uint32_t h0, l0, h1, l1;
                split2(v.x, v.y, h0, l0);
                split2(v.z, v.w, h1, l1);
                *(uint2*)(sm + SM_AHI + r * ASTR + 8 * q) = make_uint2(h0, h1);
                *(uint2*)(sm + SM_ALO + r * ASTR + 8 * q) = make_uint2(l0, l1);
            }
            __syncthreads();

            int hk = h * 256;   // byte offset into B's K dim (128 bf16)
            #pragma unroll
            for (int ks = 0; ks < 8; ks++) {
                int kb = (ks * 16 + tq * 2) * 2;   // byte offset within A half
                uint32_t ah[2][4], al[2][4];
                #pragma unroll
                for (int rt = 0; rt < 2; rt++) {
                    const char* ba = sm + SM_AHI + (rgrp + rt * 16 + quad) * ASTR + kb;
                    ah[rt][0] = *(const uint32_t*)(ba);
                    ah[rt][1] = *(const uint32_t*)(ba + 8 * ASTR);
                    ah[rt][2] = *(const uint32_t*)(ba + 16);
                    ah[rt][3] = *(const uint32_t*)(ba + 8 * ASTR + 16);
                    const char* bb = sm + SM_ALO + (rgrp + rt * 16 + quad) * ASTR + kb;
                    al[rt][0] = *(const uint32_t*)(bb);
                    al[rt][1] = *(const uint32_t*)(bb + 8 * ASTR);
                    al[rt][2] = *(const uint32_t*)(bb + 16);
                    al[rt][3] = *(const uint32_t*)(bb + 8 * ASTR + 16);
                }
                #pragma unroll
                for (int nt = 0; nt < 8; nt++) {
                    const char* bp = sm + (cgrp + nt * 8 + quad) * BSTR + hk + kb;
                    uint32_t bh0 = *(const uint32_t*)(bp + SM_BHI);
                    uint32_t bh1 = *(const uint32_t*)(bp + SM_BHI + 16);
                    mma16816(acc[0][nt], ah[0], bh0, bh1);
                    mma16816(acc[1][nt], ah[1], bh0, bh1);
                    mma16816(acc[0][nt], al[0], bh0, bh1);
                    mma16816(acc[1][nt], al[1], bh0, bh1);
                    uint32_t bl0 = *(const uint32_t*)(bp + SM_BLO);
                    uint32_t bl1 = *(const uint32_t*)(bp + SM_BLO + 16);
                    mma16816(acc[0][nt], ah[0], bl0, bl1);
                    mma16816(acc[1][nt], ah[1], bl0, bl1);
                }
            }
            __syncthreads();
        }

        // epilogue: regs -> smem (f32) -> coalesced out / pool
        #pragma unroll
        for (int rt = 0; rt < 2; rt++) {
            #pragma unroll
            for (int nt = 0; nt < 8; nt++) {
                int r0 = rgrp + rt * 16 + quad;
                int c = cgrp + nt * 8 + tq * 2;
                *(float2*)&sEpi[r0 * 132 + c] =
                    make_float2(acc[rt][nt][0], acc[rt][nt][1]);
                *(float2*)&sEpi[(r0 + 8) * 132 + c] =
                    make_float2(acc[rt][nt][2], acc[rt][nt][3]);
            }
        }
        __syncthreads();
        for (int idx = tid; idx < 128 * 32; idx += 256) {
            int r = idx >> 5, q = idx & 31;
            int grow = tb + r;
            if (grow < NN) {
                float4 v = *(float4*)&sEpi[r * 132 + 4 * q];
                float4 b = *(float4*)&sBias[4 * q];
                v.x += b.x; v.y += b.y; v.z += b.z; v.w += b.w;
                if (to_pool) {
                    float* p = g_pool + (long long)g_bat[grow] * 128 + 4 * q;
                    asm volatile("red.global.add.v4.f32 [%0], {%1,%2,%3,%4};"
                                 :: "l"(p), "f"(v.x), "f"(v.y), "f"(v.z), "f"(v.w)
                                 : "memory");
                } else {
                    ((float4*)outp)[(long long)grow * 32 + q] = v;
                }
            }
        }
        __syncthreads();
    }
}

// ---------------- head: lin1 + BN(eval) + relu + lin2 ----------------
__global__ void __launch_bounds__(128) head_kernel(
    const float* __restrict__ lin1w, const float* __restrict__ lin1b,
    const float* __restrict__ lin2w, const float* __restrict__ lin2b,
    const float* __restrict__ gamma, const float* __restrict__ beta,
    const float* __restrict__ rmean, const float* __restrict__ rvar,
    float* __restrict__ out) {
    int g = blockIdx.x;
    int c = threadIdx.x;
    __shared__ float p[128];
    __shared__ float h[128];
    p[c] = g_pool[g * 128 + c];
    __syncthreads();
    float acc = lin1b[c];
    const float* w = lin1w + c * 128;
    #pragma unroll 8
    for (int k = 0; k < 128; k++) acc += p[k] * w[k];
    acc = (acc - rmean[c]) * rsqrtf(rvar[c] + 1e-5f) * gamma[c] + beta[c];
    h[c] = fmaxf(acc, 0.f);
    __syncthreads();
    int wid = c >> 5, lane = c & 31;
    if (wid < 2) {
        const float* w2 = lin2w + wid * 128;
        float s = 0.f;
        #pragma unroll
        for (int k = lane; k < 128; k += 32) s += h[k] * w2[k];
        #pragma unroll
        for (int o = 16; o; o >>= 1) s += __shfl_xor_sync(0xffffffffu, s, o);
        if (lane == 0) out[g * 2 + wid] = s + lin2b[wid];
    }
}

// ---------------- launch ----------------
extern "C" void kernel_launch(void* const* d_in, const int* in_sizes, int n_in,
                              void* d_out, int out_size) {
    const float* x        = (const float*)d_in[0];
    const void*  ei_raw   = (const void*)d_in[1];
    const void*  bat_raw  = (const void*)d_in[2];
    const float* W1l      = (const float*)d_in[3];
    const float* b1       = (const float*)d_in[4];
    const float* W1r      = (const float*)d_in[5];
    const float* W2l      = (const float*)d_in[6];
    const float* b2       = (const float*)d_in[7];
    const float* W2r      = (const float*)d_in[8];
    const float* lin1w    = (const float*)d_in[9];
    const float* lin1b    = (const float*)d_in[10];
    const float* lin2w    = (const float*)d_in[11];
    const float* lin2b    = (const float*)d_in[12];
    const float* gamma    = (const float*)d_in[13];
    const float* beta     = (const float*)d_in[14];
    const float* rmean    = (const float*)d_in[15];
    const float* rvar     = (const float*)d_in[16];
    float* out            = (float*)d_out;

    float *agg, *h1;
    cudaGetSymbolAddress((void**)&agg, g_agg);
    cudaGetSymbolAddress((void**)&h1, g_h1);

    cudaFuncSetAttribute(conv_mma_kernel,
                         cudaFuncAttributeMaxDynamicSharedMemorySize, SM_TOTAL);

    const int agg_grid = (NE * 32 + 255) / 256;

    zero_all_kernel<<<2048, 256>>>();
    detect_kernel<<<16, 256>>>((const unsigned long long*)ei_raw,
                               (const unsigned long long*)bat_raw);
    convert_kernel<<<1024, 256>>>(ei_raw, bat_raw);
    agg_kernel<<<agg_grid, 256>>>(x, agg, 1);
    conv_mma_kernel<<<148, 256, SM_TOTAL>>>(agg, x, W1l, b1, W1r, h1, 0);
    zero_agg_kernel<<<2048, 256>>>();
    agg_kernel<<<agg_grid, 256>>>(h1, agg, 0);
    conv_mma_kernel<<<148, 256, SM_TOTAL>>>(agg, h1, W2l, b2, W2r, nullptr, 1);
    head_kernel<<<NG, 128>>>(lin1w, lin1b, lin2w, lin2b,
                             gamma, beta, rmean, rvar, out);
}

// round 5
// speedup vs baseline: 1.9961x; 1.2180x over previous
#include <cuda_runtime.h>
#include <cuda_bf16.h>
#include <cstdint>

#define NN 50000
#define NE 800000
#define NG 512

// ---------------- scratch ----------------
__device__ float g_agg[(size_t)NN * 128];   // holds MEAN after gather
__device__ float g_h1[(size_t)NN * 128];
__device__ float g_pool[NG * 128];
__device__ int g_src[NE];
__device__ int g_dst[NE];
__device__ int g_ssrc[NE];                  // src ids sorted by dst (CSR)
__device__ int g_deg[NN];
__device__ int g_off[NN + 1];
__device__ int g_cur[NN];
__device__ int g_bat[NN];
__device__ int g_eflag;
__device__ int g_bflag;

// ---------------- small zero + flag init ----------------
__global__ void zero_small_kernel() {
    int i = blockIdx.x * blockDim.x + threadIdx.x;
    int stride = gridDim.x * blockDim.x;
    if (i == 0) { g_eflag = 0; g_bflag = 0; }
    for (int j = i; j < NN; j += stride) g_deg[j] = 0;
    for (int j = i; j < NG * 128; j += stride) g_pool[j] = 0.f;
}

// Sample 64-bit words: true int64 indices are < 50000, so any word >= 2^32
// means the buffer actually holds packed int32 values.
__global__ void detect_kernel(const unsigned long long* __restrict__ e_raw,
                              const unsigned long long* __restrict__ b_raw) {
    int i = blockIdx.x * blockDim.x + threadIdx.x;
    if (i < 4096) {
        if (e_raw[i] >= (1ull << 32)) atomicExch(&g_eflag, 1);
        if (i < 2048 && b_raw[i] >= (1ull << 32)) atomicExch(&g_bflag, 1);
    }
}

// normalize indices to int32 + degree histogram
__global__ void convert_kernel(const void* __restrict__ e_raw,
                               const void* __restrict__ b_raw) {
    int eflag = g_eflag, bflag = g_bflag;
    long long i = (long long)blockIdx.x * blockDim.x + threadIdx.x;
    long long stride = (long long)gridDim.x * blockDim.x;
    for (long long e = i; e < NE; e += stride) {
        int s, d;
        if (eflag) {
            s = ((const int*)e_raw)[e];
            d = ((const int*)e_raw)[NE + e];
        } else {
            s = (int)((const long long*)e_raw)[e];
            d = (int)((const long long*)e_raw)[NE + e];
        }
        g_src[e] = s;
        g_dst[e] = d;
        atomicAdd(&g_deg[d], 1);
    }
    for (long long n = i; n < NN; n += stride) {
        g_bat[n] = bflag ? ((const int*)b_raw)[n]
                         : (int)((const long long*)b_raw)[n];
    }
}

// single-block exclusive scan of degrees -> offsets + cursors
__global__ void __launch_bounds__(1024) scan_kernel() {
    __shared__ int ssum[1024];
    int t = threadIdx.x;
    const int CH = (NN + 1023) / 1024;   // 49
    int b = t * CH;
    int e = min(b + CH, NN);
    int s = 0;
    for (int i = b; i < e; i++) s += g_deg[i];
    ssum[t] = s;
    __syncthreads();
    for (int off = 1; off < 1024; off <<= 1) {
        int u = (t >= off) ? ssum[t - off] : 0;
        __syncthreads();
        ssum[t] += u;
        __syncthreads();
    }
    int run = ssum[t] - s;               // exclusive base
    for (int i = b; i < e; i++) {
        g_off[i] = run;
        g_cur[i] = run;
        run += g_deg[i];
    }
    if (t == 1023) g_off[NN] = ssum[1023];
}

__global__ void scatter_kernel() {
    long long i = (long long)blockIdx.x * blockDim.x + threadIdx.x;
    long long stride = (long long)gridDim.x * blockDim.x;
    for (long long e = i; e < NE; e += stride) {
        int d = g_dst[e];
        int pos = atomicAdd(&g_cur[d], 1);
        g_ssrc[pos] = g_src[e];
    }
}

// ---------------- CSR gather: warp per dst node, writes MEAN ----------------
__global__ void gather_kernel(const float* __restrict__ feat,
                              float* __restrict__ aggout) {
    int lane = threadIdx.x & 31;
    int node = (int)((blockIdx.x * (long long)blockDim.x + threadIdx.x) >> 5);
    if (node >= NN) return;
    int beg = g_off[node], end = g_off[node + 1];
    float4 acc = make_float4(0.f, 0.f, 0.f, 0.f);
    int e = beg;
    for (; e + 1 < end; e += 2) {
        int s0 = g_ssrc[e], s1 = g_ssrc[e + 1];
        float4 v0 = ((const float4*)(feat + (long long)s0 * 128))[lane];
        float4 v1 = ((const float4*)(feat + (long long)s1 * 128))[lane];
        acc.x += v0.x + v1.x; acc.y += v0.y + v1.y;
        acc.z += v0.z + v1.z; acc.w += v0.w + v1.w;
    }
    if (e < end) {
        int s0 = g_ssrc[e];
        float4 v0 = ((const float4*)(feat + (long long)s0 * 128))[lane];
        acc.x += v0.x; acc.y += v0.y; acc.z += v0.z; acc.w += v0.w;
    }
    float inv = 1.f / (float)max(end - beg, 1);
    acc.x *= inv; acc.y *= inv; acc.z *= inv; acc.w *= inv;
    ((float4*)(aggout + (long long)node * 128))[lane] = acc;
}

// ---------------- helpers ----------------
__device__ __forceinline__ uint32_t smem_u32(const void* p) {
    return (uint32_t)__cvta_generic_to_shared(p);
}

__device__ __forceinline__ void split2(float a, float b, uint32_t& hi, uint32_t& lo) {
    __nv_bfloat16 ah = __float2bfloat16(a);
    __nv_bfloat16 bh = __float2bfloat16(b);
    __nv_bfloat16 al = __float2bfloat16(a - __bfloat162float(ah));
    __nv_bfloat16 bl = __float2bfloat16(b - __bfloat162float(bh));
    hi = (uint32_t)__bfloat16_as_ushort(ah) | ((uint32_t)__bfloat16_as_ushort(bh) << 16);
    lo = (uint32_t)__bfloat16_as_ushort(al) | ((uint32_t)__bfloat16_as_ushort(bl) << 16);
}

__device__ __forceinline__ void mma16816(float* c, const uint32_t* a,
                                         uint32_t b0, uint32_t b1) {
    asm volatile(
        "mma.sync.aligned.m16n8k16.row.col.f32.bf16.bf16.f32 "
        "{%0,%1,%2,%3}, {%4,%5,%6,%7}, {%8,%9}, {%0,%1,%2,%3};"
        : "+f"(c[0]), "+f"(c[1]), "+f"(c[2]), "+f"(c[3])
        : "r"(a[0]), "r"(a[1]), "r"(a[2]), "r"(a[3]), "r"(b0), "r"(b1));
}

__device__ __forceinline__ void ldsm4(uint32_t* r, uint32_t addr) {
    asm volatile("ldmatrix.sync.aligned.m8n8.x4.shared.b16 {%0,%1,%2,%3}, [%4];"
                 : "=r"(r[0]), "=r"(r[1]), "=r"(r[2]), "=r"(r[3]) : "r"(addr));
}

__device__ __forceinline__ void ldsm2(uint32_t* r, uint32_t addr) {
    asm volatile("ldmatrix.sync.aligned.m8n8.x2.shared.b16 {%0,%1}, [%2];"
                 : "=r"(r[0]), "=r"(r[1]) : "r"(addr));
}

// ---------------- smem layout (bytes) ----------------
// A: [128 rows][136 bf16] hi/lo. B: [128 n][264 bf16] hi/lo.
// Epilogue f32 [128][132] reuses the A region.
#define SM_BIAS 0
#define SM_AHI  512
#define SM_ALO  35328
#define SM_EPI  512
#define SM_BHI  70144
#define SM_BLO  137728
#define SM_TOTAL 205312
#define ASTR 272     // A row stride bytes (136 bf16)
#define BSTR 528     // B row stride bytes (264 bf16)

// ---------------- fused SAGE conv via mma.sync bf16x3 + ldmatrix ----------------
// out[i][c] = bl[c] + mean[i]@Wl[c] + xin[i]@Wr[c]   (K = 256 = [mean|x])
__global__ void __launch_bounds__(256, 1) conv_mma_kernel(
    const float* __restrict__ meanm, const float* __restrict__ xin,
    const float* __restrict__ Wl, const float* __restrict__ bl,
    const float* __restrict__ Wr, float* __restrict__ outp, int to_pool) {
    extern __shared__ char sm[];
    float* sBias = (float*)(sm + SM_BIAS);
    float* sEpi  = (float*)(sm + SM_EPI);
    int tid = threadIdx.x;
    int w = tid >> 5, lane = tid & 31;
    int quad = lane >> 2, tq = lane & 3;
    int rgrp = (w & 3) * 32;          // warp's 32 rows
    int cgrp = (w >> 2) * 64;         // warp's 64 cols

    if (tid < 128) sBias[tid] = bl[tid];

    // stage both weight matrices once: B[n][k] bf16 hi/lo, k = [Wl | Wr]
    for (int idx = tid; idx < 128 * 64; idx += 256) {
        int c = idx >> 6, p = idx & 63;
        float2 wl2 = ((const float2*)Wl)[idx];
        float2 wr2 = ((const float2*)Wr)[idx];
        uint32_t hi, lo;
        split2(wl2.x, wl2.y, hi, lo);
        *(uint32_t*)(sm + SM_BHI + c * BSTR + 4 * p) = hi;
        *(uint32_t*)(sm + SM_BLO + c * BSTR + 4 * p) = lo;
        split2(wr2.x, wr2.y, hi, lo);
        *(uint32_t*)(sm + SM_BHI + c * BSTR + 256 + 4 * p) = hi;
        *(uint32_t*)(sm + SM_BLO + c * BSTR + 256 + 4 * p) = lo;
    }
    __syncthreads();

    // ldmatrix lane address bases
    const uint32_t smb = smem_u32(sm);
    int arow = (lane & 7) + ((lane >> 3) & 1) * 8;
    uint32_t aoff = (uint32_t)((rgrp + arow) * ASTR + (lane >> 4) * 16);
    uint32_t aHi = smb + SM_AHI + aoff;
    uint32_t aLo = smb + SM_ALO + aoff;
    int bl_ = lane & 15;
    uint32_t boff = (uint32_t)((cgrp + (bl_ & 7)) * BSTR + ((bl_ >> 3) ? 16 : 0));
    uint32_t bHi = smb + SM_BHI + boff;
    uint32_t bLo = smb + SM_BLO + boff;

    for (int tile = blockIdx.x; tile * 128 < NN; tile += gridDim.x) {
        int tb = tile * 128;
        float acc[2][8][4];
        #pragma unroll
        for (int rt = 0; rt < 2; rt++)
            #pragma unroll
            for (int nt = 0; nt < 8; nt++)
                #pragma unroll
                for (int j = 0; j < 4; j++) acc[rt][nt][j] = 0.f;

        #pragma unroll
        for (int h = 0; h < 2; h++) {
            // stage A k-half: h=0 -> mean (precomputed), h=1 -> root
            for (int idx = tid; idx < 128 * 32; idx += 256) {
                int r = idx >> 5, q = idx & 31;
                int grow = tb + r;
                float4 v = make_float4(0.f, 0.f, 0.f, 0.f);
                if (grow < NN) {
                    const float* srcm = h == 0 ? meanm : xin;
                    v = ((const float4*)srcm)[(long long)grow * 32 + q];
                }
                uint32_t h0, l0, h1, l1;
                split2(v.x, v.y, h0, l0);
                split2(v.z, v.w, h1, l1);
                *(uint2*)(sm + SM_AHI + r * ASTR + 8 * q) = make_uint2(h0, h1);
                *(uint2*)(sm + SM_ALO + r * ASTR + 8 * q) = make_uint2(l0, l1);
            }
            __syncthreads();

            uint32_t hk = h * 256;   // byte offset into B's K dim
            #pragma unroll
            for (int ks = 0; ks < 8; ks++) {
                uint32_t ah[2][4], al[2][4];
                ldsm4(ah[0], aHi + ks * 32);
                ldsm4(ah[1], aHi + 16 * ASTR + ks * 32);
                ldsm4(al[0], aLo + ks * 32);
                ldsm4(al[1], aLo + 16 * ASTR + ks * 32);
                #pragma unroll
                for (int nt = 0; nt < 8; nt++) {
                    uint32_t bh[2], blo[2];
                    uint32_t bofs = (uint32_t)(nt * 8 * BSTR) + hk + ks * 32;
                    ldsm2(bh, bHi + bofs);
                    ldsm2(blo, bLo + bofs);
                    mma16816(acc[0][nt], ah[0], bh[0], bh[1]);
                    mma16816(acc[1][nt], ah[1], bh[0], bh[1]);
                    mma16816(acc[0][nt], al[0], bh[0], bh[1]);
                    mma16816(acc[1][nt], al[1], bh[0], bh[1]);
                    mma16816(acc[0][nt], ah[0], blo[0], blo[1]);
                    mma16816(acc[1][nt], ah[1], blo[0], blo[1]);
                }
            }
            __syncthreads();
        }

        // epilogue: regs -> smem (f32) -> coalesced out / pool
        #pragma unroll
        for (int rt = 0; rt < 2; rt++) {
            #pragma unroll
            for (int nt = 0; nt < 8; nt++) {
                int r0 = rgrp + rt * 16 + quad;
                int c = cgrp + nt * 8 + tq * 2;
                *(float2*)&sEpi[r0 * 132 + c] =
                    make_float2(acc[rt][nt][0], acc[rt][nt][1]);
                *(float2*)&sEpi[(r0 + 8) * 132 + c] =
                    make_float2(acc[rt][nt][2], acc[rt][nt][3]);
            }
        }
        __syncthreads();
        for (int idx = tid; idx < 128 * 32; idx += 256) {
            int r = idx >> 5, q = idx & 31;
            int grow = tb + r;
            if (grow < NN) {
                float4 v = *(float4*)&sEpi[r * 132 + 4 * q];
                float4 b = *(float4*)&sBias[4 * q];
                v.x += b.x; v.y += b.y; v.z += b.z; v.w += b.w;
                if (to_pool) {
                    float* p = g_pool + (long long)g_bat[grow] * 128 + 4 * q;
                    asm volatile("red.global.add.v4.f32 [%0], {%1,%2,%3,%4};"
                                 :: "l"(p), "f"(v.x), "f"(v.y), "f"(v.z), "f"(v.w)
                                 : "memory");
                } else {
                    ((float4*)outp)[(long long)grow * 32 + q] = v;
                }
            }
        }
        __syncthreads();
    }
}

// ---------------- head: lin1 + BN(eval) + relu + lin2 ----------------
__global__ void __launch_bounds__(128) head_kernel(
    const float* __restrict__ lin1w, const float* __restrict__ lin1b,
    const float* __restrict__ lin2w, const float* __restrict__ lin2b,
    const float* __restrict__ gamma, const float* __restrict__ beta,
    const float* __restrict__ rmean, const float* __restrict__ rvar,
    float* __restrict__ out) {
    int g = blockIdx.x;
    int c = threadIdx.x;
    __shared__ float p[128];
    __shared__ float h[128];
    p[c] = g_pool[g * 128 + c];
    __syncthreads();
    float acc = lin1b[c];
    const float* w = lin1w + c * 128;
    #pragma unroll 8
    for (int k = 0; k < 128; k++) acc += p[k] * w[k];
    acc = (acc - rmean[c]) * rsqrtf(rvar[c] + 1e-5f) * gamma[c] + beta[c];
    h[c] = fmaxf(acc, 0.f);
    __syncthreads();
    int wid = c >> 5, lane = c & 31;
    if (wid < 2) {
        const float* w2 = lin2w + wid * 128;
        float s = 0.f;
        #pragma unroll
        for (int k = lane; k < 128; k += 32) s += h[k] * w2[k];
        #pragma unroll
        for (int o = 16; o; o >>= 1) s += __shfl_xor_sync(0xffffffffu, s, o);
        if (lane == 0) out[g * 2 + wid] = s + lin2b[wid];
    }
}

// ---------------- launch ----------------
extern "C" void kernel_launch(void* const* d_in, const int* in_sizes, int n_in,
                              void* d_out, int out_size) {
    const float* x        = (const float*)d_in[0];
    const void*  ei_raw   = (const void*)d_in[1];
    const void*  bat_raw  = (const void*)d_in[2];
    const float* W1l      = (const float*)d_in[3];
    const float* b1       = (const float*)d_in[4];
    const float* W1r      = (const float*)d_in[5];
    const float* W2l      = (const float*)d_in[6];
    const float* b2       = (const float*)d_in[7];
    const float* W2r      = (const float*)d_in[8];
    const float* lin1w    = (const float*)d_in[9];
    const float* lin1b    = (const float*)d_in[10];
    const float* lin2w    = (const float*)d_in[11];
    const float* lin2b    = (const float*)d_in[12];
    const float* gamma    = (const float*)d_in[13];
    const float* beta     = (const float*)d_in[14];
    const float* rmean    = (const float*)d_in[15];
    const float* rvar     = (const float*)d_in[16];
    float* out            = (float*)d_out;

    float *agg, *h1;
    cudaGetSymbolAddress((void**)&agg, g_agg);
    cudaGetSymbolAddress((void**)&h1, g_h1);

    cudaFuncSetAttribute(conv_mma_kernel,
                         cudaFuncAttributeMaxDynamicSharedMemorySize, SM_TOTAL);

    const int gat_grid = (NN * 32 + 255) / 256;    // warp per node

    zero_small_kernel<<<256, 256>>>();
    detect_kernel<<<16, 256>>>((const unsigned long long*)ei_raw,
                               (const unsigned long long*)bat_raw);
    convert_kernel<<<1024, 256>>>(ei_raw, bat_raw);
    scan_kernel<<<1, 1024>>>();
    scatter_kernel<<<1024, 256>>>();
    gather_kernel<<<gat_grid, 256>>>(x, agg);
    conv_mma_kernel<<<148, 256, SM_TOTAL>>>(agg, x, W1l, b1, W1r, h1, 0);
    gather_kernel<<<gat_grid, 256>>>(h1, agg);
    conv_mma_kernel<<<148, 256, SM_TOTAL>>>(agg, h1, W2l, b2, W2r, nullptr, 1);
    head_kernel<<<NG, 128>>>(lin1w, lin1b, lin2w, lin2b,
                             gamma, beta, rmean, rvar, out);
}

// round 6
// speedup vs baseline: 2.6092x; 1.3071x over previous
#include <cuda_runtime.h>
#include <cuda_bf16.h>
#include <cstdint>

#define NN 50000
#define NE 800000
#define NG 512
#define NB 196            // ceil(NN/256)

// ---------------- scratch ----------------
__device__ float g_agg[(size_t)NN * 128];   // holds MEAN after gather
__device__ float g_h1[(size_t)NN * 128];
__device__ float g_pool[NG * 128];
__device__ int g_src[NE];
__device__ int g_dst[NE];
__device__ int g_ssrc[NE];                  // src ids sorted by dst (CSR)
__device__ int g_deg[NN];
__device__ int g_off[NN + 1];
__device__ int g_cur[NN];
__device__ int g_bsum[256];
__device__ int g_bbase[256];
__device__ int g_bat[NN];
__device__ int g_eflag;
__device__ int g_bflag;

// ---------------- small zero + flag init ----------------
__global__ void zero_small_kernel() {
    int i = blockIdx.x * blockDim.x + threadIdx.x;
    int stride = gridDim.x * blockDim.x;
    if (i == 0) { g_eflag = 0; g_bflag = 0; }
    for (int j = i; j < NN; j += stride) g_deg[j] = 0;
    for (int j = i; j < NG * 128; j += stride) g_pool[j] = 0.f;
}

// Sample 64-bit words: true int64 indices are < 50000, so any word >= 2^32
// means the buffer actually holds packed int32 values.
__global__ void detect_kernel(const unsigned long long* __restrict__ e_raw,
                              const unsigned long long* __restrict__ b_raw) {
    int i = blockIdx.x * blockDim.x + threadIdx.x;
    if (i < 4096) {
        if (e_raw[i] >= (1ull << 32)) atomicExch(&g_eflag, 1);
        if (i < 2048 && b_raw[i] >= (1ull << 32)) atomicExch(&g_bflag, 1);
    }
}

// normalize indices to int32 + degree histogram
__global__ void convert_kernel(const void* __restrict__ e_raw,
                               const void* __restrict__ b_raw) {
    int eflag = g_eflag, bflag = g_bflag;
    long long i = (long long)blockIdx.x * blockDim.x + threadIdx.x;
    long long stride = (long long)gridDim.x * blockDim.x;
    for (long long e = i; e < NE; e += stride) {
        int s, d;
        if (eflag) {
            s = ((const int*)e_raw)[e];
            d = ((const int*)e_raw)[NE + e];
        } else {
            s = (int)((const long long*)e_raw)[e];
            d = (int)((const long long*)e_raw)[NE + e];
        }
        g_src[e] = s;
        g_dst[e] = d;
        atomicAdd(&g_deg[d], 1);
    }
    for (long long n = i; n < NN; n += stride) {
        g_bat[n] = bflag ? ((const int*)b_raw)[n]
                         : (int)((const long long*)b_raw)[n];
    }
}

// ---------------- 3-phase deterministic scan ----------------
__global__ void __launch_bounds__(256) scan1_kernel() {   // NB blocks
    __shared__ int s[256];
    int t = threadIdx.x;
    int i = blockIdx.x * 256 + t;
    int d = (i < NN) ? g_deg[i] : 0;
    s[t] = d;
    __syncthreads();
    #pragma unroll
    for (int off = 1; off < 256; off <<= 1) {
        int v = (t >= off) ? s[t - off] : 0;
        __syncthreads();
        s[t] += v;
        __syncthreads();
    }
    if (i < NN) g_off[i] = s[t] - d;          // block-local exclusive
    if (t == 255) g_bsum[blockIdx.x] = s[255];
}

__global__ void __launch_bounds__(256) scan2_kernel() {   // 1 block
    __shared__ int s[256];
    int t = threadIdx.x;
    int v = (t < NB) ? g_bsum[t] : 0;
    s[t] = v;
    __syncthreads();
    #pragma unroll
    for (int off = 1; off < 256; off <<= 1) {
        int u = (t >= off) ? s[t - off] : 0;
        __syncthreads();
        s[t] += u;
        __syncthreads();
    }
    g_bbase[t] = s[t] - v;                    // exclusive base per block
}

__global__ void __launch_bounds__(256) scan3_kernel() {   // NB blocks
    int i = blockIdx.x * 256 + threadIdx.x;
    if (i < NN) {
        int o = g_off[i] + g_bbase[blockIdx.x];
        g_off[i] = o;
        g_cur[i] = o;
    }
    if (i == 0) g_off[NN] = NE;
}

__global__ void scatter_kernel() {
    long long i = (long long)blockIdx.x * blockDim.x + threadIdx.x;
    long long stride = (long long)gridDim.x * blockDim.x;
    for (long long e = i; e < NE; e += stride) {
        int d = g_dst[e];
        int pos = atomicAdd(&g_cur[d], 1);
        g_ssrc[pos] = g_src[e];
    }
}

// ---------------- CSR gather: warp per dst node, writes MEAN ----------------
__global__ void gather_kernel(const float* __restrict__ feat,
                              float* __restrict__ aggout) {
    int lane = threadIdx.x & 31;
    int node = (int)((blockIdx.x * (long long)blockDim.x + threadIdx.x) >> 5);
    if (node >= NN) return;
    int beg = g_off[node], end = g_off[node + 1];
    float4 acc = make_float4(0.f, 0.f, 0.f, 0.f);
    int e = beg;
    for (; e + 1 < end; e += 2) {
        int s0 = g_ssrc[e], s1 = g_ssrc[e + 1];
        float4 v0 = ((const float4*)(feat + (long long)s0 * 128))[lane];
        float4 v1 = ((const float4*)(feat + (long long)s1 * 128))[lane];
        acc.x += v0.x + v1.x; acc.y += v0.y + v1.y;
        acc.z += v0.z + v1.z; acc.w += v0.w + v1.w;
    }
    if (e < end) {
        int s0 = g_ssrc[e];
        float4 v0 = ((const float4*)(feat + (long long)s0 * 128))[lane];
        acc.x += v0.x; acc.y += v0.y; acc.z += v0.z; acc.w += v0.w;
    }
    float inv = 1.f / (float)max(end - beg, 1);
    acc.x *= inv; acc.y *= inv; acc.z *= inv; acc.w *= inv;
    ((float4*)(aggout + (long long)node * 128))[lane] = acc;
}

// ---------------- helpers ----------------
__device__ __forceinline__ uint32_t smem_u32(const void* p) {
    return (uint32_t)__cvta_generic_to_shared(p);
}

__device__ __forceinline__ void split2(float a, float b, uint32_t& hi, uint32_t& lo) {
    __nv_bfloat16 ah = __float2bfloat16(a);
    __nv_bfloat16 bh = __float2bfloat16(b);
    __nv_bfloat16 al = __float2bfloat16(a - __bfloat162float(ah));
    __nv_bfloat16 bl = __float2bfloat16(b - __bfloat162float(bh));
    hi = (uint32_t)__bfloat16_as_ushort(ah) | ((uint32_t)__bfloat16_as_ushort(bh) << 16);
    lo = (uint32_t)__bfloat16_as_ushort(al) | ((uint32_t)__bfloat16_as_ushort(bl) << 16);
}

__device__ __forceinline__ void mma16816(float* c, const uint32_t* a,
                                         uint32_t b0, uint32_t b1) {
    asm volatile(
        "mma.sync.aligned.m16n8k16.row.col.f32.bf16.bf16.f32 "
        "{%0,%1,%2,%3}, {%4,%5,%6,%7}, {%8,%9}, {%0,%1,%2,%3};"
        : "+f"(c[0]), "+f"(c[1]), "+f"(c[2]), "+f"(c[3])
        : "r"(a[0]), "r"(a[1]), "r"(a[2]), "r"(a[3]), "r"(b0), "r"(b1));
}

__device__ __forceinline__ void ldsm4(uint32_t* r, uint32_t addr) {
    asm volatile("ldmatrix.sync.aligned.m8n8.x4.shared.b16 {%0,%1,%2,%3}, [%4];"
                 : "=r"(r[0]), "=r"(r[1]), "=r"(r[2]), "=r"(r[3]) : "r"(addr));
}

__device__ __forceinline__ void ldsm2(uint32_t* r, uint32_t addr) {
    asm volatile("ldmatrix.sync.aligned.m8n8.x2.shared.b16 {%0,%1}, [%2];"
                 : "=r"(r[0]), "=r"(r[1]) : "r"(addr));
}

// ---------------- smem layout (bytes) ----------------
#define SM_BIAS 0
#define SM_AHI  512
#define SM_ALO  35328
#define SM_EPI  512
#define SM_BHI  70144
#define SM_BLO  137728
#define SM_TOTAL 205312
#define ASTR 272     // A row stride bytes (136 bf16)
#define BSTR 528     // B row stride bytes (264 bf16)

// ---------------- fused SAGE conv via mma.sync bf16x3 + ldmatrix ----------------
// out[i][c] = bl[c] + mean[i]@Wl[c] + xin[i]@Wr[c]   (K = 256 = [mean|x])
__global__ void __launch_bounds__(256, 1) conv_mma_kernel(
    const float* __restrict__ meanm, const float* __restrict__ xin,
    const float* __restrict__ Wl, const float* __restrict__ bl,
    const float* __restrict__ Wr, float* __restrict__ outp, int to_pool) {
    extern __shared__ char sm[];
    float* sBias = (float*)(sm + SM_BIAS);
    float* sEpi  = (float*)(sm + SM_EPI);
    int tid = threadIdx.x;
    int w = tid >> 5, lane = tid & 31;
    int quad = lane >> 2, tq = lane & 3;
    int rgrp = (w & 3) * 32;          // warp's 32 rows
    int cgrp = (w >> 2) * 64;         // warp's 64 cols

    if (tid < 128) sBias[tid] = bl[tid];

    // stage both weight matrices once: B[n][k] bf16 hi/lo, k = [Wl | Wr]
    for (int idx = tid; idx < 128 * 64; idx += 256) {
        int c = idx >> 6, p = idx & 63;
        float2 wl2 = ((const float2*)Wl)[idx];
        float2 wr2 = ((const float2*)Wr)[idx];
        uint32_t hi, lo;
        split2(wl2.x, wl2.y, hi, lo);
        *(uint32_t*)(sm + SM_BHI + c * BSTR + 4 * p) = hi;
        *(uint32_t*)(sm + SM_BLO + c * BSTR + 4 * p) = lo;
        split2(wr2.x, wr2.y, hi, lo);
        *(uint32_t*)(sm + SM_BHI + c * BSTR + 256 + 4 * p) = hi;
        *(uint32_t*)(sm + SM_BLO + c * BSTR + 256 + 4 * p) = lo;
    }
    __syncthreads();

    // ldmatrix lane address bases
    const uint32_t smb = smem_u32(sm);
    int arow = (lane & 7) + ((lane >> 3) & 1) * 8;
    uint32_t aoff = (uint32_t)((rgrp + arow) * ASTR + (lane >> 4) * 16);
    uint32_t aHi = smb + SM_AHI + aoff;
    uint32_t aLo = smb + SM_ALO + aoff;
    int bl_ = lane & 15;
    uint32_t boff = (uint32_t)((cgrp + (bl_ & 7)) * BSTR + ((bl_ >> 3) ? 16 : 0));
    uint32_t bHi = smb + SM_BHI + boff;
    uint32_t bLo = smb + SM_BLO + boff;

    for (int tile = blockIdx.x; tile * 128 < NN; tile += gridDim.x) {
        int tb = tile * 128;
        float acc[2][8][4];
        #pragma unroll
        for (int rt = 0; rt < 2; rt++)
            #pragma unroll
            for (int nt = 0; nt < 8; nt++)
                #pragma unroll
                for (int j = 0; j < 4; j++) acc[rt][nt][j] = 0.f;

        #pragma unroll
        for (int h = 0; h < 2; h++) {
            // stage A k-half: h=0 -> mean (precomputed), h=1 -> root
            for (int idx = tid; idx < 128 * 32; idx += 256) {
                int r = idx >> 5, q = idx & 31;
                int grow = tb + r;
                float4 v = make_float4(0.f, 0.f, 0.f, 0.f);
                if (grow < NN) {
                    const float* srcm = h == 0 ? meanm : xin;
                    v = ((const float4*)srcm)[(long long)grow * 32 + q];
                }
                uint32_t h0, l0, h1, l1;
                split2(v.x, v.y, h0, l0);
                split2(v.z, v.w, h1, l1);
                *(uint2*)(sm + SM_AHI + r * ASTR + 8 * q) = make_uint2(h0, h1);
                *(uint2*)(sm + SM_ALO + r * ASTR + 8 * q) = make_uint2(l0, l1);
            }
            __syncthreads();

            uint32_t hk = h * 256;   // byte offset into B's K dim
            #pragma unroll
            for (int ks = 0; ks < 8; ks++) {
                uint32_t ah[2][4], al[2][4];
                ldsm4(ah[0], aHi + ks * 32);
                ldsm4(ah[1], aHi + 16 * ASTR + ks * 32);
                ldsm4(al[0], aLo + ks * 32);
                ldsm4(al[1], aLo + 16 * ASTR + ks * 32);
                #pragma unroll
                for (int nt = 0; nt < 8; nt++) {
                    uint32_t bh[2], blo[2];
                    uint32_t bofs = (uint32_t)(nt * 8 * BSTR) + hk + ks * 32;
                    ldsm2(bh, bHi + bofs);
                    ldsm2(blo, bLo + bofs);
                    mma16816(acc[0][nt], ah[0], bh[0], bh[1]);
                    mma16816(acc[1][nt], ah[1], bh[0], bh[1]);
                    mma16816(acc[0][nt], al[0], bh[0], bh[1]);
                    mma16816(acc[1][nt], al[1], bh[0], bh[1]);
                    mma16816(acc[0][nt], ah[0], blo[0], blo[1]);
                    mma16816(acc[1][nt], ah[1], blo[0], blo[1]);
                }
            }
            __syncthreads();
        }

        // epilogue: regs -> smem (f32) -> coalesced out / pool
        #pragma unroll
        for (int rt = 0; rt < 2; rt++) {
            #pragma unroll
            for (int nt = 0; nt < 8; nt++) {
                int r0 = rgrp + rt * 16 + quad;
                int c = cgrp + nt * 8 + tq * 2;
                *(float2*)&sEpi[r0 * 132 + c] =
                    make_float2(acc[rt][nt][0], acc[rt][nt][1]);
                *(float2*)&sEpi[(r0 + 8) * 132 + c] =
                    make_float2(acc[rt][nt][2], acc[rt][nt][3]);
            }
        }
        __syncthreads();
        for (int idx = tid; idx < 128 * 32; idx += 256) {
            int r = idx >> 5, q = idx & 31;
            int grow = tb + r;
            if (grow < NN) {
                float4 v = *(float4*)&sEpi[r * 132 + 4 * q];
                float4 b = *(float4*)&sBias[4 * q];
                v.x += b.x; v.y += b.y; v.z += b.z; v.w += b.w;
                if (to_pool) {
                    float* p = g_pool + (long long)g_bat[grow] * 128 + 4 * q;
                    asm volatile("red.global.add.v4.f32 [%0], {%1,%2,%3,%4};"
                                 :: "l"(p), "f"(v.x), "f"(v.y), "f"(v.z), "f"(v.w)
                                 : "memory");
                } else {
                    ((float4*)outp)[(long long)grow * 32 + q] = v;
                }
            }
        }
        __syncthreads();
    }
}

// ---------------- head: lin1 + BN(eval) + relu + lin2 ----------------
__global__ void __launch_bounds__(128) head_kernel(
    const float* __restrict__ lin1w, const float* __restrict__ lin1b,
    const float* __restrict__ lin2w, const float* __restrict__ lin2b,
    const float* __restrict__ gamma, const float* __restrict__ beta,
    const float* __restrict__ rmean, const float* __restrict__ rvar,
    float* __restrict__ out) {
    int g = blockIdx.x;
    int c = threadIdx.x;
    __shared__ float p[128];
    __shared__ float h[128];
    p[c] = g_pool[g * 128 + c];
    __syncthreads();
    float acc = lin1b[c];
    const float* w = lin1w + c * 128;
    #pragma unroll 8
    for (int k = 0; k < 128; k++) acc += p[k] * w[k];
    acc = (acc - rmean[c]) * rsqrtf(rvar[c] + 1e-5f) * gamma[c] + beta[c];
    h[c] = fmaxf(acc, 0.f);
    __syncthreads();
    int wid = c >> 5, lane = c & 31;
    if (wid < 2) {
        const float* w2 = lin2w + wid * 128;
        float s = 0.f;
        #pragma unroll
        for (int k = lane; k < 128; k += 32) s += h[k] * w2[k];
        #pragma unroll
        for (int o = 16; o; o >>= 1) s += __shfl_xor_sync(0xffffffffu, s, o);
        if (lane == 0) out[g * 2 + wid] = s + lin2b[wid];
    }
}

// ---------------- launch ----------------
extern "C" void kernel_launch(void* const* d_in, const int* in_sizes, int n_in,
                              void* d_out, int out_size) {
    const float* x        = (const float*)d_in[0];
    const void*  ei_raw   = (const void*)d_in[1];
    const void*  bat_raw  = (const void*)d_in[2];
    const float* W1l      = (const float*)d_in[3];
    const float* b1       = (const float*)d_in[4];
    const float* W1r      = (const float*)d_in[5];
    const float* W2l      = (const float*)d_in[6];
    const float* b2       = (const float*)d_in[7];
    const float* W2r      = (const float*)d_in[8];
    const float* lin1w    = (const float*)d_in[9];
    const float* lin1b    = (const float*)d_in[10];
    const float* lin2w    = (const float*)d_in[11];
    const float* lin2b    = (const float*)d_in[12];
    const float* gamma    = (const float*)d_in[13];
    const float* beta     = (const float*)d_in[14];
    const float* rmean    = (const float*)d_in[15];
    const float* rvar     = (const float*)d_in[16];
    float* out            = (float*)d_out;

    float *agg, *h1;
    cudaGetSymbolAddress((void**)&agg, g_agg);
    cudaGetSymbolAddress((void**)&h1, g_h1);

    cudaFuncSetAttribute(conv_mma_kernel,
                         cudaFuncAttributeMaxDynamicSharedMemorySize, SM_TOTAL);

    const int gat_grid = (NN * 32 + 255) / 256;    // warp per node

    zero_small_kernel<<<256, 256>>>();
    detect_kernel<<<16, 256>>>((const unsigned long long*)ei_raw,
                               (const unsigned long long*)bat_raw);
    convert_kernel<<<1024, 256>>>(ei_raw, bat_raw);
    scan1_kernel<<<NB, 256>>>();
    scan2_kernel<<<1, 256>>>();
    scan3_kernel<<<NB, 256>>>();
    scatter_kernel<<<1024, 256>>>();
    gather_kernel<<<gat_grid, 256>>>(x, agg);
    conv_mma_kernel<<<148, 256, SM_TOTAL>>>(agg, x, W1l, b1, W1r, h1, 0);
    gather_kernel<<<gat_grid, 256>>>(h1, agg);
    conv_mma_kernel<<<148, 256, SM_TOTAL>>>(agg, h1, W2l, b2, W2r, nullptr, 1);
    head_kernel<<<NG, 128>>>(lin1w, lin1b, lin2w, lin2b,
                             gamma, beta, rmean, rvar, out);
}

// round 7
// speedup vs baseline: 2.6517x; 1.0163x over previous
#include <cuda_runtime.h>
#include <cuda_bf16.h>
#include <cstdint>

#define NN 50000
#define NE 800000
#define NG 512
#define NB 196            // ceil(NN/256)

// ---------------- scratch ----------------
__device__ float g_agg[(size_t)NN * 128];   // holds MEAN after gather
__device__ float g_h1[(size_t)NN * 128];
__device__ float g_pool[NG * 128];
__device__ int g_src[NE];
__device__ int g_dst[NE];
__device__ int g_ssrc[NE];                  // src ids grouped by dst (CSR)
__device__ int g_deg[NN];
__device__ int g_off[NN + 1];
__device__ int g_cur[NN];
__device__ int g_bsum[256];
__device__ int g_bat[NN];
__device__ int g_eflag = 0;   // 1 => edge_index stored as int32 (input-determined, sticky)
__device__ int g_bflag = 0;
__device__ int g_cnt1;
__device__ int g_cnt2;

// ---------------- init: zero + dtype detect ----------------
// Sample 64-bit words: true int64 indices are < 50000, so any word >= 2^32
// means the buffer actually holds packed int32 values. Flags are sticky and
// input-determined, so they are never reset (static init zeroes them once).
__global__ void init_kernel(const unsigned long long* __restrict__ e_raw,
                            const unsigned long long* __restrict__ b_raw) {
    int i = blockIdx.x * blockDim.x + threadIdx.x;
    int stride = gridDim.x * blockDim.x;
    if (i == 0) { g_cnt1 = 0; g_cnt2 = 0; }
    for (int j = i; j < NN; j += stride) g_deg[j] = 0;
    for (int j = i; j < NG * 128; j += stride) g_pool[j] = 0.f;
    if (i < 4096) {
        if (e_raw[i] >= (1ull << 32)) atomicExch(&g_eflag, 1);
        if (i < 2048 && b_raw[i] >= (1ull << 32)) atomicExch(&g_bflag, 1);
    }
}

// normalize indices to int32 + degree histogram
__global__ void convert_kernel(const void* __restrict__ e_raw,
                               const void* __restrict__ b_raw) {
    int eflag = g_eflag, bflag = g_bflag;
    long long i = (long long)blockIdx.x * blockDim.x + threadIdx.x;
    long long stride = (long long)gridDim.x * blockDim.x;
    for (long long e = i; e < NE; e += stride) {
        int s, d;
        if (eflag) {
            s = ((const int*)e_raw)[e];
            d = ((const int*)e_raw)[NE + e];
        } else {
            s = (int)((const long long*)e_raw)[e];
            d = (int)((const long long*)e_raw)[NE + e];
        }
        g_src[e] = s;
        g_dst[e] = d;
        atomicAdd(&g_deg[d], 1);
    }
    for (long long n = i; n < NN; n += stride) {
        g_bat[n] = bflag ? ((const int*)b_raw)[n]
                         : (int)((const long long*)b_raw)[n];
    }
}

// ---------------- fused scan + scatter (196 co-resident blocks) ----------------
__global__ void __launch_bounds__(256) scanscatter_kernel() {
    __shared__ int s[256];
    __shared__ int bo[256];
    __shared__ int bs[256];
    int t = threadIdx.x, b = blockIdx.x;
    int i = b * 256 + t;

    // phase 1: block-local exclusive scan of degrees
    int d = (i < NN) ? g_deg[i] : 0;
    s[t] = d;
    __syncthreads();
    #pragma unroll
    for (int off = 1; off < 256; off <<= 1) {
        int v = (t >= off) ? s[t - off] : 0;
        __syncthreads();
        s[t] += v;
        __syncthreads();
    }
    int loc = s[t] - d;
    if (t == 255) g_bsum[b] = s[255];
    __threadfence();
    __syncthreads();
    if (t == 0) {
        atomicAdd(&g_cnt1, 1);
        while (*(volatile int*)&g_cnt1 < NB) { }
    }
    __syncthreads();

    // phase 2: every block scans the 196 block sums (redundant, cheap)
    int v = (t < NB) ? g_bsum[t] : 0;
    bo[t] = v; bs[t] = v;
    __syncthreads();
    #pragma unroll
    for (int off = 1; off < 256; off <<= 1) {
        int u = (t >= off) ? bs[t - off] : 0;
        __syncthreads();
        bs[t] += u;
        __syncthreads();
    }
    int base = bs[b] - bo[b];
    if (i < NN) { int o = loc + base; g_off[i] = o; g_cur[i] = o; }
    if (i == 0) g_off[NN] = NE;
    __threadfence();
    __syncthreads();
    if (t == 0) {
        atomicAdd(&g_cnt2, 1);
        while (*(volatile int*)&g_cnt2 < NB) { }
    }
    __syncthreads();

    // phase 3: scatter src ids into CSR order
    for (int e = b * 256 + t; e < NE; e += NB * 256) {
        int dd = g_dst[e];
        int pos = atomicAdd(&g_cur[dd], 1);
        g_ssrc[pos] = g_src[e];
    }
}

// ---------------- CSR gather: warp per dst node, writes MEAN ----------------
__global__ void gather_kernel(const float* __restrict__ feat,
                              float* __restrict__ aggout) {
    int lane = threadIdx.x & 31;
    int node = (int)((blockIdx.x * (long long)blockDim.x + threadIdx.x) >> 5);
    if (node >= NN) return;
    int beg = g_off[node], end = g_off[node + 1];
    float4 acc = make_float4(0.f, 0.f, 0.f, 0.f);
    int e = beg;
    for (; e + 3 < end; e += 4) {
        int s0 = g_ssrc[e], s1 = g_ssrc[e + 1];
        int s2 = g_ssrc[e + 2], s3 = g_ssrc[e + 3];
        float4 v0 = ((const float4*)(feat + (long long)s0 * 128))[lane];
        float4 v1 = ((const float4*)(feat + (long long)s1 * 128))[lane];
        float4 v2 = ((const float4*)(feat + (long long)s2 * 128))[lane];
        float4 v3 = ((const float4*)(feat + (long long)s3 * 128))[lane];
        acc.x += (v0.x + v1.x) + (v2.x + v3.x);
        acc.y += (v0.y + v1.y) + (v2.y + v3.y);
        acc.z += (v0.z + v1.z) + (v2.z + v3.z);
        acc.w += (v0.w + v1.w) + (v2.w + v3.w);
    }
    for (; e < end; e++) {
        int s0 = g_ssrc[e];
        float4 v0 = ((const float4*)(feat + (long long)s0 * 128))[lane];
        acc.x += v0.x; acc.y += v0.y; acc.z += v0.z; acc.w += v0.w;
    }
    float inv = 1.f / (float)max(end - beg, 1);
    acc.x *= inv; acc.y *= inv; acc.z *= inv; acc.w *= inv;
    ((float4*)(aggout + (long long)node * 128))[lane] = acc;
}

// ---------------- helpers ----------------
__device__ __forceinline__ uint32_t smem_u32(const void* p) {
    return (uint32_t)__cvta_generic_to_shared(p);
}

__device__ __forceinline__ void split2(float a, float b, uint32_t& hi, uint32_t& lo) {
    __nv_bfloat16 ah = __float2bfloat16(a);
    __nv_bfloat16 bh = __float2bfloat16(b);
    __nv_bfloat16 al = __float2bfloat16(a - __bfloat162float(ah));
    __nv_bfloat16 bl = __float2bfloat16(b - __bfloat162float(bh));
    hi = (uint32_t)__bfloat16_as_ushort(ah) | ((uint32_t)__bfloat16_as_ushort(bh) << 16);
    lo = (uint32_t)__bfloat16_as_ushort(al) | ((uint32_t)__bfloat16_as_ushort(bl) << 16);
}

__device__ __forceinline__ void mma16816(float* c, const uint32_t* a,
                                         uint32_t b0, uint32_t b1) {
    asm volatile(
        "mma.sync.aligned.m16n8k16.row.col.f32.bf16.bf16.f32 "
        "{%0,%1,%2,%3}, {%4,%5,%6,%7}, {%8,%9}, {%0,%1,%2,%3};"
        : "+f"(c[0]), "+f"(c[1]), "+f"(c[2]), "+f"(c[3])
        : "r"(a[0]), "r"(a[1]), "r"(a[2]), "r"(a[3]), "r"(b0), "r"(b1));
}

__device__ __forceinline__ void ldsm4(uint32_t* r, uint32_t addr) {
    asm volatile("ldmatrix.sync.aligned.m8n8.x4.shared.b16 {%0,%1,%2,%3}, [%4];"
                 : "=r"(r[0]), "=r"(r[1]), "=r"(r[2]), "=r"(r[3]) : "r"(addr));
}

__device__ __forceinline__ void ldsm2(uint32_t* r, uint32_t addr) {
    asm volatile("ldmatrix.sync.aligned.m8n8.x2.shared.b16 {%0,%1}, [%2];"
                 : "=r"(r[0]), "=r"(r[1]) : "r"(addr));
}

// ---------------- smem layout (bytes) ----------------
#define SM_BIAS 0
#define SM_AHI  512
#define SM_ALO  35328
#define SM_EPI  512
#define SM_BHI  70144
#define SM_BLO  137728
#define SM_TOTAL 205312
#define ASTR 272     // A row stride bytes (136 bf16)
#define BSTR 528     // B row stride bytes (264 bf16)

// ---------------- fused SAGE conv via mma.sync bf16x3 + ldmatrix ----------------
// 512 threads / 16 warps: warp tile = 16 rows x 64 cols.
// out[i][c] = bl[c] + mean[i]@Wl[c] + xin[i]@Wr[c]   (K = 256 = [mean|x])
__global__ void __launch_bounds__(512, 1) conv_mma_kernel(
    const float* __restrict__ meanm, const float* __restrict__ xin,
    const float* __restrict__ Wl, const float* __restrict__ bl,
    const float* __restrict__ Wr, float* __restrict__ outp, int to_pool) {
    extern __shared__ char sm[];
    float* sBias = (float*)(sm + SM_BIAS);
    float* sEpi  = (float*)(sm + SM_EPI);
    int tid = threadIdx.x;
    int w = tid >> 5, lane = tid & 31;
    int quad = lane >> 2, tq = lane & 3;
    int rgrp = (w & 7) * 16;          // warp's 16 rows
    int cgrp = (w >> 3) * 64;         // warp's 64 cols

    if (tid < 128) sBias[tid] = bl[tid];

    // stage both weight matrices once: B[n][k] bf16 hi/lo, k = [Wl | Wr]
    for (int idx = tid; idx < 128 * 64; idx += 512) {
        int c = idx >> 6, p = idx & 63;
        float2 wl2 = ((const float2*)Wl)[idx];
        float2 wr2 = ((const float2*)Wr)[idx];
        uint32_t hi, lo;
        split2(wl2.x, wl2.y, hi, lo);
        *(uint32_t*)(sm + SM_BHI + c * BSTR + 4 * p) = hi;
        *(uint32_t*)(sm + SM_BLO + c * BSTR + 4 * p) = lo;
        split2(wr2.x, wr2.y, hi, lo);
        *(uint32_t*)(sm + SM_BHI + c * BSTR + 256 + 4 * p) = hi;
        *(uint32_t*)(sm + SM_BLO + c * BSTR + 256 + 4 * p) = lo;
    }
    __syncthreads();

    // ldmatrix lane address bases
    const uint32_t smb = smem_u32(sm);
    int arow = (lane & 7) + ((lane >> 3) & 1) * 8;
    uint32_t aoff = (uint32_t)((rgrp + arow) * ASTR + (lane >> 4) * 16);
    uint32_t aHi = smb + SM_AHI + aoff;
    uint32_t aLo = smb + SM_ALO + aoff;
    int bl_ = lane & 15;
    uint32_t boff = (uint32_t)((cgrp + (bl_ & 7)) * BSTR + ((bl_ >> 3) ? 16 : 0));
    uint32_t bHi = smb + SM_BHI + boff;
    uint32_t bLo = smb + SM_BLO + boff;

    for (int tile = blockIdx.x; tile * 128 < NN; tile += gridDim.x) {
        int tb = tile * 128;
        float acc[8][4];
        #pragma unroll
        for (int nt = 0; nt < 8; nt++)
            #pragma unroll
            for (int j = 0; j < 4; j++) acc[nt][j] = 0.f;

        #pragma unroll
        for (int h = 0; h < 2; h++) {
            // stage A k-half: h=0 -> mean (precomputed), h=1 -> root
            for (int idx = tid; idx < 128 * 32; idx += 512) {
                int r = idx >> 5, q = idx & 31;
                int grow = tb + r;
                float4 v = make_float4(0.f, 0.f, 0.f, 0.f);
                if (grow < NN) {
                    const float* srcm = h == 0 ? meanm : xin;
                    v = ((const float4*)srcm)[(long long)grow * 32 + q];
                }
                uint32_t h0, l0, h1, l1;
                split2(v.x, v.y, h0, l0);
                split2(v.z, v.w, h1, l1);
                *(uint2*)(sm + SM_AHI + r * ASTR + 8 * q) = make_uint2(h0, h1);
                *(uint2*)(sm + SM_ALO + r * ASTR + 8 * q) = make_uint2(l0, l1);
            }
            __syncthreads();

            uint32_t hk = h * 256;   // byte offset into B's K dim
            #pragma unroll
            for (int ks = 0; ks < 8; ks++) {
                uint32_t ah[4], al[4];
                ldsm4(ah, aHi + ks * 32);
                ldsm4(al, aLo + ks * 32);
                #pragma unroll
                for (int nt = 0; nt < 8; nt++) {
                    uint32_t bh[2], blo[2];
                    uint32_t bofs = (uint32_t)(nt * 8 * BSTR) + hk + ks * 32;
                    ldsm2(bh, bHi + bofs);
                    ldsm2(blo, bLo + bofs);
                    mma16816(acc[nt], ah, bh[0], bh[1]);
                    mma16816(acc[nt], al, bh[0], bh[1]);
                    mma16816(acc[nt], ah, blo[0], blo[1]);
                }
            }
            __syncthreads();
        }

        // epilogue: regs -> smem (f32) -> coalesced out / pool
        #pragma unroll
        for (int nt = 0; nt < 8; nt++) {
            int r0 = rgrp + quad;
            int c = cgrp + nt * 8 + tq * 2;
            *(float2*)&sEpi[r0 * 132 + c] = make_float2(acc[nt][0], acc[nt][1]);
            *(float2*)&sEpi[(r0 + 8) * 132 + c] = make_float2(acc[nt][2], acc[nt][3]);
        }
        __syncthreads();
        for (int idx = tid; idx < 128 * 32; idx += 512) {
            int r = idx >> 5, q = idx & 31;
            int grow = tb + r;
            if (grow < NN) {
                float4 v = *(float4*)&sEpi[r * 132 + 4 * q];
                float4 b = *(float4*)&sBias[4 * q];
                v.x += b.x; v.y += b.y; v.z += b.z; v.w += b.w;
                if (to_pool) {
                    float* p = g_pool + (long long)g_bat[grow] * 128 + 4 * q;
                    asm volatile("red.global.add.v4.f32 [%0], {%1,%2,%3,%4};"
                                 :: "l"(p), "f"(v.x), "f"(v.y), "f"(v.z), "f"(v.w)
                                 : "memory");
                } else {
                    ((float4*)outp)[(long long)grow * 32 + q] = v;
                }
            }
        }
        __syncthreads();
    }
}

// ---------------- head: lin1 + BN(eval) + relu + lin2 ----------------
__global__ void __launch_bounds__(128) head_kernel(
    const float* __restrict__ lin1w, const float* __restrict__ lin1b,
    const float* __restrict__ lin2w, const float* __restrict__ lin2b,
    const float* __restrict__ gamma, const float* __restrict__ beta,
    const float* __restrict__ rmean, const float* __restrict__ rvar,
    float* __restrict__ out) {
    int g = blockIdx.x;
    int c = threadIdx.x;
    __shared__ float p[128];
    __shared__ float h[128];
    p[c] = g_pool[g * 128 + c];
    __syncthreads();
    float acc = lin1b[c];
    const float* w = lin1w + c * 128;
    #pragma unroll 8
    for (int k = 0; k < 128; k++) acc += p[k] * w[k];
    acc = (acc - rmean[c]) * rsqrtf(rvar[c] + 1e-5f) * gamma[c] + beta[c];
    h[c] = fmaxf(acc, 0.f);
    __syncthreads();
    int wid = c >> 5, lane = c & 31;
    if (wid < 2) {
        const float* w2 = lin2w + wid * 128;
        float s = 0.f;
        #pragma unroll
        for (int k = lane; k < 128; k += 32) s += h[k] * w2[k];
        #pragma unroll
        for (int o = 16; o; o >>= 1) s += __shfl_xor_sync(0xffffffffu, s, o);
        if (lane == 0) out[g * 2 + wid] = s + lin2b[wid];
    }
}

// ---------------- launch ----------------
extern "C" void kernel_launch(void* const* d_in, const int* in_sizes, int n_in,
                              void* d_out, int out_size) {
    const float* x        = (const float*)d_in[0];
    const void*  ei_raw   = (const void*)d_in[1];
    const void*  bat_raw  = (const void*)d_in[2];
    const float* W1l      = (const float*)d_in[3];
    const float* b1       = (const float*)d_in[4];
    const float* W1r      = (const float*)d_in[5];
    const float* W2l      = (const float*)d_in[6];
    const float* b2       = (const float*)d_in[7];
    const float* W2r      = (const float*)d_in[8];
    const float* lin1w    = (const float*)d_in[9];
    const float* lin1b    = (const float*)d_in[10];
    const float* lin2w    = (const float*)d_in[11];
    const float* lin2b    = (const float*)d_in[12];
    const float* gamma    = (const float*)d_in[13];
    const float* beta     = (const float*)d_in[14];
    const float* rmean    = (const float*)d_in[15];
    const float* rvar     = (const float*)d_in[16];
    float* out            = (float*)d_out;

    float *agg, *h1;
    cudaGetSymbolAddress((void**)&agg, g_agg);
    cudaGetSymbolAddress((void**)&h1, g_h1);

    cudaFuncSetAttribute(conv_mma_kernel,
                         cudaFuncAttributeMaxDynamicSharedMemorySize, SM_TOTAL);

    const int gat_grid = (NN * 32 + 255) / 256;    // warp per node

    init_kernel<<<256, 256>>>((const unsigned long long*)ei_raw,
                              (const unsigned long long*)bat_raw);
    convert_kernel<<<1024, 256>>>(ei_raw, bat_raw);
    scanscatter_kernel<<<NB, 256>>>();
    gather_kernel<<<gat_grid, 256>>>(x, agg);
    conv_mma_kernel<<<148, 512, SM_TOTAL>>>(agg, x, W1l, b1, W1r, h1, 0);
    gather_kernel<<<gat_grid, 256>>>(h1, agg);
    conv_mma_kernel<<<148, 512, SM_TOTAL>>>(agg, h1, W2l, b2, W2r, nullptr, 1);
    head_kernel<<<NG, 128>>>(lin1w, lin1b, lin2w, lin2b,
                             gamma, beta, rmean, rvar, out);
}

// round 8
// speedup vs baseline: 2.6740x; 1.0084x over previous
#include <cuda_runtime.h>
#include <cuda_bf16.h>
#include <cstdint>

#define NN 50000
#define NE 800000
#define NG 512
#define NB 196            // ceil(NN/256)

// ---------------- scratch ----------------
__device__ float g_agg[(size_t)NN * 128];   // holds MEAN after gather
__device__ float g_h1[(size_t)NN * 128];
__device__ float g_pool[NG * 128];
__device__ int g_src[NE];
__device__ int g_dst[NE];
__device__ int g_ssrc[NE];                  // src ids grouped by dst (CSR)
__device__ int g_deg[NN];
__device__ int g_off[NN + 1];
__device__ int g_cur[NN];
__device__ int g_bsum[256];
__device__ int g_bat[NN];
__device__ int g_eflag = 0;   // 1 => edge_index stored as int32 (input-determined, sticky)
__device__ int g_bflag = 0;
__device__ int g_cnt1;
__device__ int g_cnt2;

// ---------------- init: zero + dtype detect ----------------
// Sample 64-bit words: true int64 indices are < 50000, so any word >= 2^32
// means the buffer actually holds packed int32 values. Flags are sticky and
// input-determined, so they are never reset (static init zeroes them once).
__global__ void init_kernel(const unsigned long long* __restrict__ e_raw,
                            const unsigned long long* __restrict__ b_raw) {
    int i = blockIdx.x * blockDim.x + threadIdx.x;
    int stride = gridDim.x * blockDim.x;
    if (i == 0) { g_cnt1 = 0; g_cnt2 = 0; }
    for (int j = i; j < NN; j += stride) g_deg[j] = 0;
    for (int j = i; j < NG * 128; j += stride) g_pool[j] = 0.f;
    if (i < 4096) {
        if (e_raw[i] >= (1ull << 32)) atomicExch(&g_eflag, 1);
        if (i < 2048 && b_raw[i] >= (1ull << 32)) atomicExch(&g_bflag, 1);
    }
}

// normalize indices to int32 + degree histogram
__global__ void convert_kernel(const void* __restrict__ e_raw,
                               const void* __restrict__ b_raw) {
    int eflag = g_eflag, bflag = g_bflag;
    long long i = (long long)blockIdx.x * blockDim.x + threadIdx.x;
    long long stride = (long long)gridDim.x * blockDim.x;
    for (long long e = i; e < NE; e += stride) {
        int s, d;
        if (eflag) {
            s = ((const int*)e_raw)[e];
            d = ((const int*)e_raw)[NE + e];
        } else {
            s = (int)((const long long*)e_raw)[e];
            d = (int)((const long long*)e_raw)[NE + e];
        }
        g_src[e] = s;
        g_dst[e] = d;
        atomicAdd(&g_deg[d], 1);
    }
    for (long long n = i; n < NN; n += stride) {
        g_bat[n] = bflag ? ((const int*)b_raw)[n]
                         : (int)((const long long*)b_raw)[n];
    }
}

// ---------------- fused scan + scatter (co-resident blocks) ----------------
__global__ void __launch_bounds__(256) scanscatter_kernel() {
    __shared__ int s[256];
    __shared__ int bo[256];
    __shared__ int bs[256];
    int t = threadIdx.x, b = blockIdx.x;
    int i = b * 256 + t;

    // phase 1: block-local exclusive scan of degrees
    int d = (i < NN) ? g_deg[i] : 0;
    s[t] = d;
    __syncthreads();
    #pragma unroll
    for (int off = 1; off < 256; off <<= 1) {
        int v = (t >= off) ? s[t - off] : 0;
        __syncthreads();
        s[t] += v;
        __syncthreads();
    }
    int loc = s[t] - d;
    if (t == 255) g_bsum[b] = s[255];
    __threadfence();
    __syncthreads();
    if (t == 0) {
        atomicAdd(&g_cnt1, 1);
        while (*(volatile int*)&g_cnt1 < NB) { __nanosleep(64); }
    }
    __syncthreads();

    // phase 2: every block scans the block sums (redundant, cheap)
    int v = (t < NB) ? g_bsum[t] : 0;
    bo[t] = v; bs[t] = v;
    __syncthreads();
    #pragma unroll
    for (int off = 1; off < 256; off <<= 1) {
        int u = (t >= off) ? bs[t - off] : 0;
        __syncthreads();
        bs[t] += u;
        __syncthreads();
    }
    int base = bs[b] - bo[b];
    if (i < NN) { int o = loc + base; g_off[i] = o; g_cur[i] = o; }
    if (i == 0) g_off[NN] = NE;
    __threadfence();
    __syncthreads();
    if (t == 0) {
        atomicAdd(&g_cnt2, 1);
        while (*(volatile int*)&g_cnt2 < NB) { __nanosleep(64); }
    }
    __syncthreads();

    // phase 3: scatter src ids into CSR order
    for (int e = b * 256 + t; e < NE; e += NB * 256) {
        int dd = g_dst[e];
        int pos = atomicAdd(&g_cur[dd], 1);
        g_ssrc[pos] = g_src[e];
    }
}

// ---------------- CSR gather: warp per dst node, writes MEAN ----------------
__global__ void gather_kernel(const float* __restrict__ feat,
                              float* __restrict__ aggout) {
    int lane = threadIdx.x & 31;
    int node = (int)((blockIdx.x * (long long)blockDim.x + threadIdx.x) >> 5);
    if (node >= NN) return;
    int beg = g_off[node], end = g_off[node + 1];
    float4 acc = make_float4(0.f, 0.f, 0.f, 0.f);
    int e = beg;
    for (; e + 7 < end; e += 8) {
        float4 v[8];
        #pragma unroll
        for (int j = 0; j < 8; j++) {
            int sj = g_ssrc[e + j];
            v[j] = ((const float4*)(feat + (long long)sj * 128))[lane];
        }
        #pragma unroll
        for (int j = 0; j < 8; j++) {
            acc.x += v[j].x; acc.y += v[j].y; acc.z += v[j].z; acc.w += v[j].w;
        }
    }
    for (; e + 3 < end; e += 4) {
        float4 v[4];
        #pragma unroll
        for (int j = 0; j < 4; j++) {
            int sj = g_ssrc[e + j];
            v[j] = ((const float4*)(feat + (long long)sj * 128))[lane];
        }
        #pragma unroll
        for (int j = 0; j < 4; j++) {
            acc.x += v[j].x; acc.y += v[j].y; acc.z += v[j].z; acc.w += v[j].w;
        }
    }
    for (; e < end; e++) {
        int s0 = g_ssrc[e];
        float4 v0 = ((const float4*)(feat + (long long)s0 * 128))[lane];
        acc.x += v0.x; acc.y += v0.y; acc.z += v0.z; acc.w += v0.w;
    }
    float inv = 1.f / (float)max(end - beg, 1);
    acc.x *= inv; acc.y *= inv; acc.z *= inv; acc.w *= inv;
    ((float4*)(aggout + (long long)node * 128))[lane] = acc;
}

// ---------------- helpers ----------------
__device__ __forceinline__ uint32_t smem_u32(const void* p) {
    return (uint32_t)__cvta_generic_to_shared(p);
}

__device__ __forceinline__ void split2(float a, float b, uint32_t& hi, uint32_t& lo) {
    __nv_bfloat16 ah = __float2bfloat16(a);
    __nv_bfloat16 bh = __float2bfloat16(b);
    __nv_bfloat16 al = __float2bfloat16(a - __bfloat162float(ah));
    __nv_bfloat16 bl = __float2bfloat16(b - __bfloat162float(bh));
    hi = (uint32_t)__bfloat16_as_ushort(ah) | ((uint32_t)__bfloat16_as_ushort(bh) << 16);
    lo = (uint32_t)__bfloat16_as_ushort(al) | ((uint32_t)__bfloat16_as_ushort(bl) << 16);
}

__device__ __forceinline__ void mma16816(float* c, const uint32_t* a,
                                         uint32_t b0, uint32_t b1) {
    asm volatile(
        "mma.sync.aligned.m16n8k16.row.col.f32.bf16.bf16.f32 "
        "{%0,%1,%2,%3}, {%4,%5,%6,%7}, {%8,%9}, {%0,%1,%2,%3};"
        : "+f"(c[0]), "+f"(c[1]), "+f"(c[2]), "+f"(c[3])
        : "r"(a[0]), "r"(a[1]), "r"(a[2]), "r"(a[3]), "r"(b0), "r"(b1));
}

__device__ __forceinline__ void ldsm4(uint32_t* r, uint32_t addr) {
    asm volatile("ldmatrix.sync.aligned.m8n8.x4.shared.b16 {%0,%1,%2,%3}, [%4];"
                 : "=r"(r[0]), "=r"(r[1]), "=r"(r[2]), "=r"(r[3]) : "r"(addr));
}

// ---------------- smem layout (bytes) ----------------
#define SM_BIAS 0
#define SM_AHI  512
#define SM_ALO  35328
#define SM_EPI  512
#define SM_BHI  70144
#define SM_BLO  137728
#define SM_TOTAL 205312
#define ASTR 272     // A row stride bytes (136 bf16)
#define BSTR 528     // B row stride bytes (264 bf16)

// ---------------- fused SAGE conv via mma.sync bf16x3 + ldmatrix ----------------
// 512 threads / 16 warps: warp tile = 32 rows x 32 cols (rt=2, nt=4).
// B fragments loaded pairwise with ldmatrix.x4 (2 n-tiles per instruction).
// out[i][c] = bl[c] + mean[i]@Wl[c] + xin[i]@Wr[c]   (K = 256 = [mean|x])
__global__ void __launch_bounds__(512, 1) conv_mma_kernel(
    const float* __restrict__ meanm, const float* __restrict__ xin,
    const float* __restrict__ Wl, const float* __restrict__ bl,
    const float* __restrict__ Wr, float* __restrict__ outp, int to_pool) {
    extern __shared__ char sm[];
    float* sBias = (float*)(sm + SM_BIAS);
    float* sEpi  = (float*)(sm + SM_EPI);
    int tid = threadIdx.x;
    int w = tid >> 5, lane = tid & 31;
    int quad = lane >> 2, tq = lane & 3;
    int rgrp = (w & 3) * 32;          // warp's 32 rows
    int cgrp = (w >> 2) * 32;         // warp's 32 cols

    if (tid < 128) sBias[tid] = bl[tid];

    // stage both weight matrices once: B[n][k] bf16 hi/lo, k = [Wl | Wr]
    for (int idx = tid; idx < 128 * 64; idx += 512) {
        int c = idx >> 6, p = idx & 63;
        float2 wl2 = ((const float2*)Wl)[idx];
        float2 wr2 = ((const float2*)Wr)[idx];
        uint32_t hi, lo;
        split2(wl2.x, wl2.y, hi, lo);
        *(uint32_t*)(sm + SM_BHI + c * BSTR + 4 * p) = hi;
        *(uint32_t*)(sm + SM_BLO + c * BSTR + 4 * p) = lo;
        split2(wr2.x, wr2.y, hi, lo);
        *(uint32_t*)(sm + SM_BHI + c * BSTR + 256 + 4 * p) = hi;
        *(uint32_t*)(sm + SM_BLO + c * BSTR + 256 + 4 * p) = lo;
    }
    __syncthreads();

    const uint32_t smb = smem_u32(sm);
    // A ldmatrix.x4 lane base: 16 rows x (two k8 groups)
    int arow = (lane & 7) + ((lane >> 3) & 1) * 8;
    uint32_t aoff = (uint32_t)((rgrp + arow) * ASTR + (lane >> 4) * 16);
    uint32_t aHi = smb + SM_AHI + aoff;
    uint32_t aLo = smb + SM_ALO + aoff;
    // B ldmatrix.x4 lane base: matrices {nt,k0},{nt,k1},{nt+1,k0},{nt+1,k1}
    int brow = (lane & 7) + ((lane >> 4) & 1) * 8;   // +8 rows for m in {2,3}
    uint32_t boff = (uint32_t)((cgrp + brow) * BSTR + ((lane >> 3) & 1) * 16);
    uint32_t bHi = smb + SM_BHI + boff;
    uint32_t bLo = smb + SM_BLO + boff;

    for (int tile = blockIdx.x; tile * 128 < NN; tile += gridDim.x) {
        int tb = tile * 128;
        float acc[2][4][4];
        #pragma unroll
        for (int rt = 0; rt < 2; rt++)
            #pragma unroll
            for (int nt = 0; nt < 4; nt++)
                #pragma unroll
                for (int j = 0; j < 4; j++) acc[rt][nt][j] = 0.f;

        #pragma unroll
        for (int h = 0; h < 2; h++) {
            // stage A k-half: h=0 -> mean (precomputed), h=1 -> root
            for (int idx = tid; idx < 128 * 32; idx += 512) {
                int r = idx >> 5, q = idx & 31;
                int grow = tb + r;
                float4 v = make_float4(0.f, 0.f, 0.f, 0.f);
                if (grow < NN) {
                    const float* srcm = h == 0 ? meanm : xin;
                    v = ((const float4*)srcm)[(long long)grow * 32 + q];
                }
                uint32_t h0, l0, h1, l1;
                split2(v.x, v.y, h0, l0);
                split2(v.z, v.w, h1, l1);
                *(uint2*)(sm + SM_AHI + r * ASTR + 8 * q) = make_uint2(h0, h1);
                *(uint2*)(sm + SM_ALO + r * ASTR + 8 * q) = make_uint2(l0, l1);
            }
            __syncthreads();

            uint32_t hk = h * 256;   // byte offset into B's K dim
            #pragma unroll
            for (int ks = 0; ks < 8; ks++) {
                uint32_t ah0[4], ah1[4], al0[4], al1[4];
                ldsm4(ah0, aHi + ks * 32);
                ldsm4(ah1, aHi + 16 * ASTR + ks * 32);
                ldsm4(al0, aLo + ks * 32);
                ldsm4(al1, aLo + 16 * ASTR + ks * 32);
                #pragma unroll
                for (int ntp = 0; ntp < 2; ntp++) {
                    uint32_t bh[4], blo[4];
                    uint32_t bofs = (uint32_t)(ntp * 16 * BSTR) + hk + ks * 32;
                    ldsm4(bh, bHi + bofs);
                    ldsm4(blo, bLo + bofs);
                    int n0 = ntp * 2, n1 = ntp * 2 + 1;
                    mma16816(acc[0][n0], ah0, bh[0], bh[1]);
                    mma16816(acc[1][n0], ah1, bh[0], bh[1]);
                    mma16816(acc[0][n1], ah0, bh[2], bh[3]);
                    mma16816(acc[1][n1], ah1, bh[2], bh[3]);
                    mma16816(acc[0][n0], al0, bh[0], bh[1]);
                    mma16816(acc[1][n0], al1, bh[0], bh[1]);
                    mma16816(acc[0][n1], al0, bh[2], bh[3]);
                    mma16816(acc[1][n1], al1, bh[2], bh[3]);
                    mma16816(acc[0][n0], ah0, blo[0], blo[1]);
                    mma16816(acc[1][n0], ah1, blo[0], blo[1]);
                    mma16816(acc[0][n1], ah0, blo[2], blo[3]);
                    mma16816(acc[1][n1], ah1, blo[2], blo[3]);
                }
            }
            __syncthreads();
        }

        // epilogue: regs -> smem (f32) -> coalesced out / pool
        #pragma unroll
        for (int rt = 0; rt < 2; rt++) {
            #pragma unroll
            for (int nt = 0; nt < 4; nt++) {
                int r0 = rgrp + rt * 16 + quad;
                int c = cgrp + nt * 8 + tq * 2;
                *(float2*)&sEpi[r0 * 132 + c] =
                    make_float2(acc[rt][nt][0], acc[rt][nt][1]);
                *(float2*)&sEpi[(r0 + 8) * 132 + c] =
                    make_float2(acc[rt][nt][2], acc[rt][nt][3]);
            }
        }
        __syncthreads();
        for (int idx = tid; idx < 128 * 32; idx += 512) {
            int r = idx >> 5, q = idx & 31;
            int grow = tb + r;
            if (grow < NN) {
                float4 v = *(float4*)&sEpi[r * 132 + 4 * q];
                float4 b = *(float4*)&sBias[4 * q];
                v.x += b.x; v.y += b.y; v.z += b.z; v.w += b.w;
                if (to_pool) {
                    float* p = g_pool + (long long)g_bat[grow] * 128 + 4 * q;
                    asm volatile("red.global.add.v4.f32 [%0], {%1,%2,%3,%4};"
                                 :: "l"(p), "f"(v.x), "f"(v.y), "f"(v.z), "f"(v.w)
                                 : "memory");
                } else {
                    ((float4*)outp)[(long long)grow * 32 + q] = v;
                }
            }
        }
        __syncthreads();
    }
}

// ---------------- head: lin1 + BN(eval) + relu + lin2 ----------------
__global__ void __launch_bounds__(128) head_kernel(
    const float* __restrict__ lin1w, const float* __restrict__ lin1b,
    const float* __restrict__ lin2w, const float* __restrict__ lin2b,
    const float* __restrict__ gamma, const float* __restrict__ beta,
    const float* __restrict__ rmean, const float* __restrict__ rvar,
    float* __restrict__ out) {
    int g = blockIdx.x;
    int c = threadIdx.x;
    __shared__ float p[128];
    __shared__ float h[128];
    p[c] = g_pool[g * 128 + c];
    __syncthreads();
    float acc = lin1b[c];
    const float* w = lin1w + c * 128;
    #pragma unroll 8
    for (int k = 0; k < 128; k++) acc += p[k] * w[k];
    acc = (acc - rmean[c]) * rsqrtf(rvar[c] + 1e-5f) * gamma[c] + beta[c];
    h[c] = fmaxf(acc, 0.f);
    __syncthreads();
    int wid = c >> 5, lane = c & 31;
    if (wid < 2) {
        const float* w2 = lin2w + wid * 128;
        float s = 0.f;
        #pragma unroll
        for (int k = lane; k < 128; k += 32) s += h[k] * w2[k];
        #pragma unroll
        for (int o = 16; o; o >>= 1) s += __shfl_xor_sync(0xffffffffu, s, o);
        if (lane == 0) out[g * 2 + wid] = s + lin2b[wid];
    }
}

// ---------------- launch ----------------
extern "C" void kernel_launch(void* const* d_in, const int* in_sizes, int n_in,
                              void* d_out, int out_size) {
    const float* x        = (const float*)d_in[0];
    const void*  ei_raw   = (const void*)d_in[1];
    const void*  bat_raw  = (const void*)d_in[2];
    const float* W1l      = (const float*)d_in[3];
    const float* b1       = (const float*)d_in[4];
    const float* W1r      = (const float*)d_in[5];
    const float* W2l      = (const float*)d_in[6];
    const float* b2       = (const float*)d_in[7];
    const float* W2r      = (const float*)d_in[8];
    const float* lin1w    = (const float*)d_in[9];
    const float* lin1b    = (const float*)d_in[10];
    const float* lin2w    = (const float*)d_in[11];
    const float* lin2b    = (const float*)d_in[12];
    const float* gamma    = (const float*)d_in[13];
    const float* beta     = (const float*)d_in[14];
    const float* rmean    = (const float*)d_in[15];
    const float* rvar     = (const float*)d_in[16];
    float* out            = (float*)d_out;

    float *agg, *h1;
    cudaGetSymbolAddress((void**)&agg, g_agg);
    cudaGetSymbolAddress((void**)&h1, g_h1);

    cudaFuncSetAttribute(conv_mma_kernel,
                         cudaFuncAttributeMaxDynamicSharedMemorySize, SM_TOTAL);

    const int gat_grid = (NN * 32 + 255) / 256;    // warp per node

    init_kernel<<<256, 256>>>((const unsigned long long*)ei_raw,
                              (const unsigned long long*)bat_raw);
    convert_kernel<<<1024, 256>>>(ei_raw, bat_raw);
    scanscatter_kernel<<<NB, 256>>>();
    gather_kernel<<<gat_grid, 256>>>(x, agg);
    conv_mma_kernel<<<148, 512, SM_TOTAL>>>(agg, x, W1l, b1, W1r, h1, 0);
    gather_kernel<<<gat_grid, 256>>>(h1, agg);
    conv_mma_kernel<<<148, 512, SM_TOTAL>>>(agg, h1, W2l, b2, W2r, nullptr, 1);
    head_kernel<<<NG, 128>>>(lin1w, lin1b, lin2w, lin2b,
                             gamma, beta, rmean, rvar, out);
}